// round 2
// baseline (speedup 1.0000x reference)
#include <cuda_runtime.h>

// Problem constants
#define B_TOT 512
#define N_TOK 145
#define M_TOK 144
#define C_DIM 512
#define H_NUM 8
#define HD    64
#define NWIN  4
#define ROWS  (B_TOT * N_TOK)              // 74240
#define QKV_ELEMS (B_TOT * H_NUM * N_TOK * HD)  // 38,010,880

// Scratch (device globals; no allocation allowed)
__device__ float g_q[QKV_ELEMS];
__device__ float g_k[QKV_ELEMS];
__device__ float g_v[QKV_ELEMS];
__device__ float g_opre[ROWS * C_DIM];

// ---------------------------------------------------------------------------
// Tiled fp32 NT GEMM: out[m,n] = sum_k A[m,k] * W[n,k] + bias[n]
// A: [74240, 512] row-major, W: [512, 512] row-major.
// sel 0/1/2: scatter output into g_q/g_k/g_v with [B_,H,N,hd] layout.
// sel 3:     A = g_opre, plain row-major output to outPlain.
// ---------------------------------------------------------------------------
__global__ void __launch_bounds__(256) sgemm_nt(
    const float* __restrict__ Ain,
    const float* __restrict__ W,
    const float* __restrict__ bias,
    float* __restrict__ outPlain,
    int sel)
{
    const float* A = (sel == 3) ? g_opre : Ain;
    __shared__ __align__(16) float As[8][128];
    __shared__ __align__(16) float Bs[8][128];

    int tid = threadIdx.x;
    int tx = tid & 15, ty = tid >> 4;
    int m0 = blockIdx.y * 128, n0 = blockIdx.x * 128;
    int lrow = tid >> 1;
    int lcol = (tid & 1) * 4;

    const float* Ap = A + (size_t)(m0 + lrow) * C_DIM + lcol;
    const float* Wp = W + (size_t)(n0 + lrow) * C_DIM + lcol;

    float acc[8][8];
#pragma unroll
    for (int i = 0; i < 8; i++)
#pragma unroll
        for (int j = 0; j < 8; j++) acc[i][j] = 0.f;

    for (int k0 = 0; k0 < C_DIM; k0 += 8) {
        float4 av = *(const float4*)(Ap + k0);
        float4 wv = *(const float4*)(Wp + k0);
        __syncthreads();
        As[lcol + 0][lrow] = av.x; As[lcol + 1][lrow] = av.y;
        As[lcol + 2][lrow] = av.z; As[lcol + 3][lrow] = av.w;
        Bs[lcol + 0][lrow] = wv.x; Bs[lcol + 1][lrow] = wv.y;
        Bs[lcol + 2][lrow] = wv.z; Bs[lcol + 3][lrow] = wv.w;
        __syncthreads();
#pragma unroll
        for (int kk = 0; kk < 8; kk++) {
            float a[8], b[8];
#pragma unroll
            for (int i = 0; i < 8; i++) a[i] = As[kk][ty * 8 + i];
#pragma unroll
            for (int j = 0; j < 8; j++) b[j] = Bs[kk][tx * 8 + j];
#pragma unroll
            for (int i = 0; i < 8; i++)
#pragma unroll
                for (int j = 0; j < 8; j++)
                    acc[i][j] += a[i] * b[j];
        }
    }

    int gn0 = n0 + tx * 8;
    float bvreg[8];
#pragma unroll
    for (int j = 0; j < 8; j++) bvreg[j] = bias[gn0 + j];

#pragma unroll
    for (int i = 0; i < 8; i++) {
        int gm = m0 + ty * 8 + i;
        float4 v0 = make_float4(acc[i][0] + bvreg[0], acc[i][1] + bvreg[1],
                                acc[i][2] + bvreg[2], acc[i][3] + bvreg[3]);
        float4 v1 = make_float4(acc[i][4] + bvreg[4], acc[i][5] + bvreg[5],
                                acc[i][6] + bvreg[6], acc[i][7] + bvreg[7]);
        float* dst;
        if (sel == 3) {
            dst = outPlain + (size_t)gm * C_DIM + gn0;
        } else {
            int b_ = gm / N_TOK;
            int t  = gm - b_ * N_TOK;
            int h  = gn0 >> 6;
            int d  = gn0 & 63;
            float* base = (sel == 0) ? g_q : (sel == 1) ? g_k : g_v;
            dst = base + ((((size_t)b_ * H_NUM + h) * N_TOK + t) * HD + d);
        }
        *(float4*)dst = v0;
        *(float4*)(dst + 4) = v1;
    }
}

// ---------------------------------------------------------------------------
// Window attention: one block per (b_, h). K/V staged in padded smem.
// 4 warps x 4 rows per pass (rows 0..143; row 144 is overwritten by gx later).
// ---------------------------------------------------------------------------
#define KSTRIDE 65
#define ATTN_SMEM_FLOATS (2 * N_TOK * KSTRIDE + 1024 + 4 * 4 * 148)
#define ATTN_SMEM_BYTES  (ATTN_SMEM_FLOATS * 4)

__global__ void __launch_bounds__(128) attn_kernel(
    const float* __restrict__ mask,
    const float* __restrict__ rpb)
{
    extern __shared__ __align__(16) float sm[];
    float* Ks = sm;
    float* Vs = Ks + N_TOK * KSTRIDE;
    float* Qs = Vs + N_TOK * KSTRIDE;     // 4 warps * 4 rows * 64
    float* Ps = Qs + 1024;                // 4 warps * 4 rows * 148

    int bh = blockIdx.x;
    int b_ = bh >> 3, h = bh & 7, w = b_ & 3;
    const float* gK = g_k + (size_t)bh * (N_TOK * HD);
    const float* gV = g_v + (size_t)bh * (N_TOK * HD);
    const float* gQ = g_q + (size_t)bh * (N_TOK * HD);
    int tid = threadIdx.x, lane = tid & 31, warp = tid >> 5;

    for (int i = tid; i < N_TOK * HD; i += 128) {
        int n = i >> 6, d = i & 63;
        Ks[n * KSTRIDE + d] = gK[i];
        Vs[n * KSTRIDE + d] = gV[i];
    }
    __syncthreads();

    float* Qw = Qs + warp * 256;
    float* Pw = Ps + warp * (4 * 148);
    const float* mrow_base = mask + (size_t)w * (N_TOK * N_TOK);

    const float* kb[5];
    int jvalid[5];
#pragma unroll
    for (int jj = 0; jj < 5; jj++) {
        int j = lane + jj * 32;
        jvalid[jj] = (j < N_TOK);
        kb[jj] = Ks + (jvalid[jj] ? j : M_TOK) * KSTRIDE;
    }

    for (int iter = 0; iter < 9; iter++) {
        int row0 = iter * 16 + warp * 4;
        for (int i = lane; i < 256; i += 32) Qw[i] = gQ[row0 * HD + i];
        __syncwarp();

        float acc[4][5];
#pragma unroll
        for (int r = 0; r < 4; r++)
#pragma unroll
            for (int jj = 0; jj < 5; jj++) acc[r][jj] = 0.f;

#pragma unroll 8
        for (int d = 0; d < 64; d++) {
            float q0 = Qw[d], q1 = Qw[64 + d], q2 = Qw[128 + d], q3 = Qw[192 + d];
#pragma unroll
            for (int jj = 0; jj < 5; jj++) {
                float kv = kb[jj][d];
                acc[0][jj] += q0 * kv;
                acc[1][jj] += q1 * kv;
                acc[2][jj] += q2 * kv;
                acc[3][jj] += q3 * kv;
            }
        }

#pragma unroll
        for (int r = 0; r < 4; r++) {
            int row = row0 + r;
            int rH = row / 12, rW = row - rH * 12;
            const float* mrow = mrow_base + row * N_TOK;
            float l[5];
#pragma unroll
            for (int jj = 0; jj < 5; jj++) {
                int j = lane + jj * 32;
                if (j < N_TOK) {
                    float val = acc[r][jj] * 0.125f + mrow[j];
                    if (j < M_TOK) {
                        int jH = j / 12, jW = j - jH * 12;
                        int idx = (rH - jH + 11) * 23 + (rW - jW + 11);
                        val += rpb[idx * H_NUM + h];
                    }
                    l[jj] = val;
                } else {
                    l[jj] = -1e30f;
                }
            }
            float mx = l[0];
#pragma unroll
            for (int jj = 1; jj < 5; jj++) mx = fmaxf(mx, l[jj]);
#pragma unroll
            for (int o = 16; o > 0; o >>= 1)
                mx = fmaxf(mx, __shfl_xor_sync(0xffffffffu, mx, o));
            float s = 0.f;
#pragma unroll
            for (int jj = 0; jj < 5; jj++) {
                float e = __expf(l[jj] - mx);
                l[jj] = e;
                s += e;
            }
#pragma unroll
            for (int o = 16; o > 0; o >>= 1)
                s += __shfl_xor_sync(0xffffffffu, s, o);
            float inv = 1.f / s;
#pragma unroll
            for (int jj = 0; jj < 5; jj++) {
                int j = lane + jj * 32;
                if (j < N_TOK) Pw[r * 148 + j] = l[jj] * inv;
            }
        }
        __syncwarp();

        float o00 = 0.f, o01 = 0.f, o10 = 0.f, o11 = 0.f;
        float o20 = 0.f, o21 = 0.f, o30 = 0.f, o31 = 0.f;
#pragma unroll 5
        for (int k = 0; k < N_TOK; k++) {
            float v0 = Vs[k * KSTRIDE + lane];
            float v1 = Vs[k * KSTRIDE + 32 + lane];
            float p0 = Pw[k], p1 = Pw[148 + k], p2 = Pw[296 + k], p3 = Pw[444 + k];
            o00 += p0 * v0; o01 += p0 * v1;
            o10 += p1 * v0; o11 += p1 * v1;
            o20 += p2 * v0; o21 += p2 * v1;
            o30 += p3 * v0; o31 += p3 * v1;
        }
        {
            float* dst = g_opre + (size_t)(b_ * N_TOK + row0) * C_DIM + h * HD;
            dst[lane] = o00; dst[lane + 32] = o01; dst += C_DIM;
            dst[lane] = o10; dst[lane + 32] = o11; dst += C_DIM;
            dst[lane] = o20; dst[lane + 32] = o21; dst += C_DIM;
            dst[lane] = o30; dst[lane + 32] = o31;
        }
        __syncwarp();
    }
}

// ---------------------------------------------------------------------------
// Global-token redistribution: one block per (b, h).
// Recomputes last-row logits across all 4 windows, 577-way softmax,
// weighted sum of V, writes row 144 of g_opre for all 4 windows.
// ---------------------------------------------------------------------------
__global__ void __launch_bounds__(128) gx_kernel(const float* __restrict__ mask)
{
    __shared__ __align__(16) float L[580];   // 577 used; padded for alignment
    __shared__ __align__(16) float Qg[256];
    __shared__ __align__(16) float red[128];
    __shared__ float s_inv;

    int b = blockIdx.x >> 3, h = blockIdx.x & 7;
    int tid = threadIdx.x;

    for (int i = tid; i < 256; i += 128) {
        int w = i >> 6, d = i & 63;
        Qg[i] = g_q[(((size_t)(b * 4 + w) * H_NUM + h) * N_TOK + M_TOK) * HD + d];
    }
    __syncthreads();

    for (int idx = tid; idx < 577; idx += 128) {
        if (idx < 576) {
            int w = idx / 144, n = idx - w * 144;
            const float4* kp = (const float4*)(g_k +
                (((size_t)(b * 4 + w) * H_NUM + h) * N_TOK + n) * HD);
            const float4* qp = (const float4*)(Qg + w * 64);
            float dot = 0.f;
#pragma unroll
            for (int t = 0; t < 16; t++) {
                float4 kv = kp[t], qv = qp[t];
                dot += kv.x * qv.x + kv.y * qv.y + kv.z * qv.z + kv.w * qv.w;
            }
            L[idx] = dot * 0.125f +
                     mask[(size_t)w * (N_TOK * N_TOK) + M_TOK * N_TOK + n];
        } else {
            float s = 0.f;
            for (int w = 0; w < 4; w++) {
                const float4* kp = (const float4*)(g_k +
                    (((size_t)(b * 4 + w) * H_NUM + h) * N_TOK + M_TOK) * HD);
                const float4* qp = (const float4*)(Qg + w * 64);
                float dot = 0.f;
#pragma unroll
                for (int t = 0; t < 16; t++) {
                    float4 kv = kp[t], qv = qp[t];
                    dot += kv.x * qv.x + kv.y * qv.y + kv.z * qv.z + kv.w * qv.w;
                }
                s += dot * 0.125f +
                     mask[(size_t)w * (N_TOK * N_TOK) + M_TOK * N_TOK + M_TOK];
            }
            L[576] = s * 0.25f;
        }
    }
    __syncthreads();

    float mx = -1e30f;
    for (int idx = tid; idx < 577; idx += 128) mx = fmaxf(mx, L[idx]);
    red[tid] = mx;
    __syncthreads();
    for (int s2 = 64; s2 > 0; s2 >>= 1) {
        if (tid < s2) red[tid] = fmaxf(red[tid], red[tid + s2]);
        __syncthreads();
    }
    mx = red[0];
    __syncthreads();

    float ps = 0.f;
    for (int idx = tid; idx < 577; idx += 128) {
        float e = __expf(L[idx] - mx);
        L[idx] = e;
        ps += e;
    }
    red[tid] = ps;
    __syncthreads();
    for (int s2 = 64; s2 > 0; s2 >>= 1) {
        if (tid < s2) red[tid] += red[tid + s2];
        __syncthreads();
    }
    if (tid == 0) s_inv = 1.f / red[0];
    __syncthreads();

    int d = tid & 63, half = tid >> 6;
    float acc = 0.f;
    for (int w = 0; w < 4; w++) {
        const float* vb = g_v + (((size_t)(b * 4 + w) * H_NUM + h) * N_TOK) * HD;
        for (int n = half; n < M_TOK; n += 2)
            acc += L[w * 144 + n] * vb[n * HD + d];
        if ((w & 1) == half)
            acc += L[576] * vb[M_TOK * HD + d];
    }
    red[tid] = acc;
    __syncthreads();
    if (half == 0) {
        float tot = (red[tid] + red[tid + 64]) * s_inv;
#pragma unroll
        for (int w = 0; w < 4; w++)
            g_opre[(size_t)((b * 4 + w) * N_TOK + M_TOK) * C_DIM + h * HD + d] = tot;
    }
}

// ---------------------------------------------------------------------------
extern "C" void kernel_launch(void* const* d_in, const int* in_sizes, int n_in,
                              void* d_out, int out_size)
{
    const float* x    = (const float*)d_in[0];
    const float* mask = (const float*)d_in[1];
    const float* rpb  = (const float*)d_in[2];
    const float* Wq   = (const float*)d_in[3];
    const float* bq   = (const float*)d_in[4];
    const float* Wk   = (const float*)d_in[5];
    const float* bk   = (const float*)d_in[6];
    const float* Wv   = (const float*)d_in[7];
    const float* bv   = (const float*)d_in[8];
    const float* Wo   = (const float*)d_in[9];
    const float* bo   = (const float*)d_in[10];
    float* out = (float*)d_out;

    dim3 gg(4, 580, 1);   // 512/128 x 74240/128
    sgemm_nt<<<gg, 256>>>(x, Wq, bq, nullptr, 0);
    sgemm_nt<<<gg, 256>>>(x, Wk, bk, nullptr, 1);
    sgemm_nt<<<gg, 256>>>(x, Wv, bv, nullptr, 2);

    cudaFuncSetAttribute(attn_kernel, cudaFuncAttributeMaxDynamicSharedMemorySize,
                         ATTN_SMEM_BYTES);
    attn_kernel<<<4096, 128, ATTN_SMEM_BYTES>>>(mask, rpb);
    gx_kernel<<<1024, 128>>>(mask);

    sgemm_nt<<<gg, 256>>>(x, Wo, bo, out, 3);
}

// round 3
// speedup vs baseline: 1.8964x; 1.8964x over previous
#include <cuda_runtime.h>

// Problem constants
#define B_TOT 512
#define N_TOK 145
#define M_TOK 144
#define C_DIM 512
#define H_NUM 8
#define HD    64
#define NWIN  4
#define ROWS  (B_TOT * N_TOK)              // 74240
#define QKV_ELEMS (B_TOT * H_NUM * N_TOK * HD)  // 38,010,880

// Scratch (device globals; no allocation allowed)
__device__ float g_q[QKV_ELEMS];
__device__ float g_k[QKV_ELEMS];
__device__ float g_v[QKV_ELEMS];
__device__ float g_opre[ROWS * C_DIM];

// ---------------------------------------------------------------------------
// TF32 tensor-core NT GEMM: out[m,n] = sum_k A[m,k] * W[n,k] + bias[n]
// A: [74240, 512] row-major, W: [512, 512] row-major.
// Block tile 128x128, 8 warps (2x4), warp tile 64x32, mma.m16n8k8.tf32.
// smem layout [k][m] (stride 136) with XOR-8 swizzle on m keyed by (k>>2)&3:
// conflict-free for both transpose stores and fragment loads.
// sel 0/1/2: scatter output into g_q/g_k/g_v ([B_,H,N,hd]); sel 3: plain.
// ---------------------------------------------------------------------------
#define KC   16
#define SMS  136
#define NSTG (C_DIM / KC)   // 32

__device__ __forceinline__ unsigned to_tf32(float x) {
    unsigned r;
    asm("cvt.rna.tf32.f32 %0, %1;" : "=r"(r) : "f"(x));
    return r;
}

__device__ __forceinline__ void mma_tf32(float* d,
    unsigned a0, unsigned a1, unsigned a2, unsigned a3,
    unsigned b0, unsigned b1)
{
    asm volatile(
        "mma.sync.aligned.m16n8k8.row.col.f32.tf32.tf32.f32 "
        "{%0,%1,%2,%3}, {%4,%5,%6,%7}, {%8,%9}, {%0,%1,%2,%3};"
        : "+f"(d[0]), "+f"(d[1]), "+f"(d[2]), "+f"(d[3])
        : "r"(a0), "r"(a1), "r"(a2), "r"(a3), "r"(b0), "r"(b1));
}

__global__ void __launch_bounds__(256, 2) tgemm(
    const float* __restrict__ Ain,
    const float* __restrict__ W,
    const float* __restrict__ bias,
    float* __restrict__ outPlain,
    int sel)
{
    const float* A = (sel == 3) ? g_opre : Ain;
    __shared__ __align__(16) float As[2][KC][SMS];
    __shared__ __align__(16) float Bs[2][KC][SMS];

    int tid = threadIdx.x;
    int lane = tid & 31, warp = tid >> 5;
    int wm = warp & 1, wn = warp >> 1;               // warps: 2(M) x 4(N)
    int m0 = blockIdx.y * 128, n0 = blockIdx.x * 128;

    // Global->smem mapping: thread handles float4 at (row, lcol) and (row+64, lcol)
    int lrow = tid >> 2;             // 0..63
    int lcol = (tid & 3) * 4;        // 0,4,8,12
    int swz  = (tid & 3) << 3;       // swizzle for stored k-group ((k>>2)&3)<<3

    const float* Ap0 = A + (size_t)(m0 + lrow) * C_DIM + lcol;
    const float* Ap1 = A + (size_t)(m0 + lrow + 64) * C_DIM + lcol;
    const float* Wp0 = W + (size_t)(n0 + lrow) * C_DIM + lcol;
    const float* Wp1 = W + (size_t)(n0 + lrow + 64) * C_DIM + lcol;

    float acc[4][4][4];
#pragma unroll
    for (int mt = 0; mt < 4; mt++)
#pragma unroll
        for (int nt = 0; nt < 4; nt++)
#pragma unroll
            for (int i = 0; i < 4; i++) acc[mt][nt][i] = 0.f;

    // Prologue: stage 0
    {
        float4 a0v = *(const float4*)(Ap0);
        float4 a1v = *(const float4*)(Ap1);
        float4 b0v = *(const float4*)(Wp0);
        float4 b1v = *(const float4*)(Wp1);
        const float* af0 = &a0v.x; const float* af1 = &a1v.x;
        const float* bf0 = &b0v.x; const float* bf1 = &b1v.x;
#pragma unroll
        for (int i = 0; i < 4; i++) {
            ((unsigned*)As[0][lcol + i])[lrow ^ swz]        = to_tf32(af0[i]);
            ((unsigned*)As[0][lcol + i])[(lrow + 64) ^ swz] = to_tf32(af1[i]);
            ((unsigned*)Bs[0][lcol + i])[lrow ^ swz]        = to_tf32(bf0[i]);
            ((unsigned*)Bs[0][lcol + i])[(lrow + 64) ^ swz] = to_tf32(bf1[i]);
        }
    }
    __syncthreads();

    int c = lane & 3, lr = lane >> 2;
    int cur = 0;

    for (int s = 0; s < NSTG; s++) {
        float4 pa0, pa1, pb0, pb1;
        if (s + 1 < NSTG) {
            int k0 = (s + 1) * KC;
            pa0 = *(const float4*)(Ap0 + k0);
            pa1 = *(const float4*)(Ap1 + k0);
            pb0 = *(const float4*)(Wp0 + k0);
            pb1 = *(const float4*)(Wp1 + k0);
        }

        // Compute 2 ksteps on buffer cur
#pragma unroll
        for (int ks = 0; ks < 2; ks++) {
            int kk = ks * 8 + c;
            int sw0 = ((2 * ks) & 3) << 3;
            int sw1 = ((2 * ks + 1) & 3) << 3;
            unsigned af[4][4], bf[4][2];
#pragma unroll
            for (int mt = 0; mt < 4; mt++) {
                int mr = wm * 64 + mt * 16 + lr;
                af[mt][0] = __float_as_uint(As[cur][kk][mr ^ sw0]);
                af[mt][1] = __float_as_uint(As[cur][kk][(mr + 8) ^ sw0]);
                af[mt][2] = __float_as_uint(As[cur][kk + 4][mr ^ sw1]);
                af[mt][3] = __float_as_uint(As[cur][kk + 4][(mr + 8) ^ sw1]);
            }
#pragma unroll
            for (int nt = 0; nt < 4; nt++) {
                int nr = wn * 32 + nt * 8 + lr;
                bf[nt][0] = __float_as_uint(Bs[cur][kk][nr ^ sw0]);
                bf[nt][1] = __float_as_uint(Bs[cur][kk + 4][nr ^ sw1]);
            }
#pragma unroll
            for (int mt = 0; mt < 4; mt++)
#pragma unroll
                for (int nt = 0; nt < 4; nt++)
                    mma_tf32(acc[mt][nt], af[mt][0], af[mt][1], af[mt][2],
                             af[mt][3], bf[nt][0], bf[nt][1]);
        }

        if (s + 1 < NSTG) {
            int nxt = cur ^ 1;
            __syncthreads();
            const float* af0 = &pa0.x; const float* af1 = &pa1.x;
            const float* bf0 = &pb0.x; const float* bf1 = &pb1.x;
#pragma unroll
            for (int i = 0; i < 4; i++) {
                ((unsigned*)As[nxt][lcol + i])[lrow ^ swz]        = to_tf32(af0[i]);
                ((unsigned*)As[nxt][lcol + i])[(lrow + 64) ^ swz] = to_tf32(af1[i]);
                ((unsigned*)Bs[nxt][lcol + i])[lrow ^ swz]        = to_tf32(bf0[i]);
                ((unsigned*)Bs[nxt][lcol + i])[(lrow + 64) ^ swz] = to_tf32(bf1[i]);
            }
            __syncthreads();
            cur = nxt;
        }
    }

    // Epilogue: bias add + scatter
    float* qkvbase = (sel == 0) ? g_q : (sel == 1) ? g_k : g_v;
#pragma unroll
    for (int mt = 0; mt < 4; mt++) {
#pragma unroll
        for (int half = 0; half < 2; half++) {
            int gm = m0 + wm * 64 + mt * 16 + lr + half * 8;
            int b_ = gm / N_TOK;
            int t  = gm - b_ * N_TOK;
#pragma unroll
            for (int nt = 0; nt < 4; nt++) {
                int gn = n0 + wn * 32 + nt * 8 + c * 2;
                float v0 = acc[mt][nt][half * 2 + 0] + bias[gn];
                float v1 = acc[mt][nt][half * 2 + 1] + bias[gn + 1];
                float* dst;
                if (sel == 3) {
                    dst = outPlain + (size_t)gm * C_DIM + gn;
                } else {
                    int h = gn >> 6, d = gn & 63;
                    dst = qkvbase +
                          ((((size_t)b_ * H_NUM + h) * N_TOK + t) * HD + d);
                }
                *(float2*)dst = make_float2(v0, v1);
            }
        }
    }
}

// ---------------------------------------------------------------------------
// Window attention: one block per (b_, h). K/V staged in padded smem.
// ---------------------------------------------------------------------------
#define KSTRIDE 65
#define ATTN_SMEM_FLOATS (2 * N_TOK * KSTRIDE + 1024 + 4 * 4 * 148)
#define ATTN_SMEM_BYTES  (ATTN_SMEM_FLOATS * 4)

__global__ void __launch_bounds__(128) attn_kernel(
    const float* __restrict__ mask,
    const float* __restrict__ rpb)
{
    extern __shared__ __align__(16) float sm[];
    float* Ks = sm;
    float* Vs = Ks + N_TOK * KSTRIDE;
    float* Qs = Vs + N_TOK * KSTRIDE;
    float* Ps = Qs + 1024;

    int bh = blockIdx.x;
    int b_ = bh >> 3, h = bh & 7, w = b_ & 3;
    const float* gK = g_k + (size_t)bh * (N_TOK * HD);
    const float* gV = g_v + (size_t)bh * (N_TOK * HD);
    const float* gQ = g_q + (size_t)bh * (N_TOK * HD);
    int tid = threadIdx.x, lane = tid & 31, warp = tid >> 5;

    for (int i = tid; i < N_TOK * HD; i += 128) {
        int n = i >> 6, d = i & 63;
        Ks[n * KSTRIDE + d] = gK[i];
        Vs[n * KSTRIDE + d] = gV[i];
    }
    __syncthreads();

    float* Qw = Qs + warp * 256;
    float* Pw = Ps + warp * (4 * 148);
    const float* mrow_base = mask + (size_t)w * (N_TOK * N_TOK);

    const float* kb[5];
#pragma unroll
    for (int jj = 0; jj < 5; jj++) {
        int j = lane + jj * 32;
        kb[jj] = Ks + ((j < N_TOK) ? j : M_TOK) * KSTRIDE;
    }

    for (int iter = 0; iter < 9; iter++) {
        int row0 = iter * 16 + warp * 4;
        for (int i = lane; i < 256; i += 32) Qw[i] = gQ[row0 * HD + i];
        __syncwarp();

        float acc[4][5];
#pragma unroll
        for (int r = 0; r < 4; r++)
#pragma unroll
            for (int jj = 0; jj < 5; jj++) acc[r][jj] = 0.f;

#pragma unroll 8
        for (int d = 0; d < 64; d++) {
            float q0 = Qw[d], q1 = Qw[64 + d], q2 = Qw[128 + d], q3 = Qw[192 + d];
#pragma unroll
            for (int jj = 0; jj < 5; jj++) {
                float kv = kb[jj][d];
                acc[0][jj] += q0 * kv;
                acc[1][jj] += q1 * kv;
                acc[2][jj] += q2 * kv;
                acc[3][jj] += q3 * kv;
            }
        }

#pragma unroll
        for (int r = 0; r < 4; r++) {
            int row = row0 + r;
            int rH = row / 12, rW = row - rH * 12;
            const float* mrow = mrow_base + row * N_TOK;
            float l[5];
#pragma unroll
            for (int jj = 0; jj < 5; jj++) {
                int j = lane + jj * 32;
                if (j < N_TOK) {
                    float val = acc[r][jj] * 0.125f + mrow[j];
                    if (j < M_TOK) {
                        int jH = j / 12, jW = j - jH * 12;
                        int idx = (rH - jH + 11) * 23 + (rW - jW + 11);
                        val += rpb[idx * H_NUM + h];
                    }
                    l[jj] = val;
                } else {
                    l[jj] = -1e30f;
                }
            }
            float mx = l[0];
#pragma unroll
            for (int jj = 1; jj < 5; jj++) mx = fmaxf(mx, l[jj]);
#pragma unroll
            for (int o = 16; o > 0; o >>= 1)
                mx = fmaxf(mx, __shfl_xor_sync(0xffffffffu, mx, o));
            float s = 0.f;
#pragma unroll
            for (int jj = 0; jj < 5; jj++) {
                float e = __expf(l[jj] - mx);
                l[jj] = e;
                s += e;
            }
#pragma unroll
            for (int o = 16; o > 0; o >>= 1)
                s += __shfl_xor_sync(0xffffffffu, s, o);
            float inv = 1.f / s;
#pragma unroll
            for (int jj = 0; jj < 5; jj++) {
                int j = lane + jj * 32;
                if (j < N_TOK) Pw[r * 148 + j] = l[jj] * inv;
            }
        }
        __syncwarp();

        float o00 = 0.f, o01 = 0.f, o10 = 0.f, o11 = 0.f;
        float o20 = 0.f, o21 = 0.f, o30 = 0.f, o31 = 0.f;
#pragma unroll 5
        for (int k = 0; k < N_TOK; k++) {
            float v0 = Vs[k * KSTRIDE + lane];
            float v1 = Vs[k * KSTRIDE + 32 + lane];
            float p0 = Pw[k], p1 = Pw[148 + k], p2 = Pw[296 + k], p3 = Pw[444 + k];
            o00 += p0 * v0; o01 += p0 * v1;
            o10 += p1 * v0; o11 += p1 * v1;
            o20 += p2 * v0; o21 += p2 * v1;
            o30 += p3 * v0; o31 += p3 * v1;
        }
        {
            float* dst = g_opre + (size_t)(b_ * N_TOK + row0) * C_DIM + h * HD;
            dst[lane] = o00; dst[lane + 32] = o01; dst += C_DIM;
            dst[lane] = o10; dst[lane + 32] = o11; dst += C_DIM;
            dst[lane] = o20; dst[lane + 32] = o21; dst += C_DIM;
            dst[lane] = o30; dst[lane + 32] = o31;
        }
        __syncwarp();
    }
}

// ---------------------------------------------------------------------------
// Global-token redistribution: one block per (b, h).
// ---------------------------------------------------------------------------
__global__ void __launch_bounds__(128) gx_kernel(const float* __restrict__ mask)
{
    __shared__ __align__(16) float L[580];
    __shared__ __align__(16) float Qg[256];
    __shared__ __align__(16) float red[128];
    __shared__ float s_inv;

    int b = blockIdx.x >> 3, h = blockIdx.x & 7;
    int tid = threadIdx.x;

    for (int i = tid; i < 256; i += 128) {
        int w = i >> 6, d = i & 63;
        Qg[i] = g_q[(((size_t)(b * 4 + w) * H_NUM + h) * N_TOK + M_TOK) * HD + d];
    }
    __syncthreads();

    for (int idx = tid; idx < 577; idx += 128) {
        if (idx < 576) {
            int w = idx / 144, n = idx - w * 144;
            const float4* kp = (const float4*)(g_k +
                (((size_t)(b * 4 + w) * H_NUM + h) * N_TOK + n) * HD);
            const float4* qp = (const float4*)(Qg + w * 64);
            float dot = 0.f;
#pragma unroll
            for (int t = 0; t < 16; t++) {
                float4 kv = kp[t], qv = qp[t];
                dot += kv.x * qv.x + kv.y * qv.y + kv.z * qv.z + kv.w * qv.w;
            }
            L[idx] = dot * 0.125f +
                     mask[(size_t)w * (N_TOK * N_TOK) + M_TOK * N_TOK + n];
        } else {
            float s = 0.f;
            for (int w = 0; w < 4; w++) {
                const float4* kp = (const float4*)(g_k +
                    (((size_t)(b * 4 + w) * H_NUM + h) * N_TOK + M_TOK) * HD);
                const float4* qp = (const float4*)(Qg + w * 64);
                float dot = 0.f;
#pragma unroll
                for (int t = 0; t < 16; t++) {
                    float4 kv = kp[t], qv = qp[t];
                    dot += kv.x * qv.x + kv.y * qv.y + kv.z * qv.z + kv.w * qv.w;
                }
                s += dot * 0.125f +
                     mask[(size_t)w * (N_TOK * N_TOK) + M_TOK * N_TOK + M_TOK];
            }
            L[576] = s * 0.25f;
        }
    }
    __syncthreads();

    float mx = -1e30f;
    for (int idx = tid; idx < 577; idx += 128) mx = fmaxf(mx, L[idx]);
    red[tid] = mx;
    __syncthreads();
    for (int s2 = 64; s2 > 0; s2 >>= 1) {
        if (tid < s2) red[tid] = fmaxf(red[tid], red[tid + s2]);
        __syncthreads();
    }
    mx = red[0];
    __syncthreads();

    float ps = 0.f;
    for (int idx = tid; idx < 577; idx += 128) {
        float e = __expf(L[idx] - mx);
        L[idx] = e;
        ps += e;
    }
    red[tid] = ps;
    __syncthreads();
    for (int s2 = 64; s2 > 0; s2 >>= 1) {
        if (tid < s2) red[tid] += red[tid + s2];
        __syncthreads();
    }
    if (tid == 0) s_inv = 1.f / red[0];
    __syncthreads();

    int d = tid & 63, half = tid >> 6;
    float acc = 0.f;
    for (int w = 0; w < 4; w++) {
        const float* vb = g_v + (((size_t)(b * 4 + w) * H_NUM + h) * N_TOK) * HD;
        for (int n = half; n < M_TOK; n += 2)
            acc += L[w * 144 + n] * vb[n * HD + d];
        if ((w & 1) == half)
            acc += L[576] * vb[M_TOK * HD + d];
    }
    red[tid] = acc;
    __syncthreads();
    if (half == 0) {
        float tot = (red[tid] + red[tid + 64]) * s_inv;
#pragma unroll
        for (int w = 0; w < 4; w++)
            g_opre[(size_t)((b * 4 + w) * N_TOK + M_TOK) * C_DIM + h * HD + d] = tot;
    }
}

// ---------------------------------------------------------------------------
extern "C" void kernel_launch(void* const* d_in, const int* in_sizes, int n_in,
                              void* d_out, int out_size)
{
    const float* x    = (const float*)d_in[0];
    const float* mask = (const float*)d_in[1];
    const float* rpb  = (const float*)d_in[2];
    const float* Wq   = (const float*)d_in[3];
    const float* bq   = (const float*)d_in[4];
    const float* Wk   = (const float*)d_in[5];
    const float* bk   = (const float*)d_in[6];
    const float* Wv   = (const float*)d_in[7];
    const float* bv   = (const float*)d_in[8];
    const float* Wo   = (const float*)d_in[9];
    const float* bo   = (const float*)d_in[10];
    float* out = (float*)d_out;

    dim3 gg(4, 580, 1);   // 512/128 x 74240/128
    tgemm<<<gg, 256>>>(x, Wq, bq, nullptr, 0);
    tgemm<<<gg, 256>>>(x, Wk, bk, nullptr, 1);
    tgemm<<<gg, 256>>>(x, Wv, bv, nullptr, 2);

    cudaFuncSetAttribute(attn_kernel, cudaFuncAttributeMaxDynamicSharedMemorySize,
                         ATTN_SMEM_BYTES);
    attn_kernel<<<4096, 128, ATTN_SMEM_BYTES>>>(mask, rpb);
    gx_kernel<<<1024, 128>>>(mask);

    tgemm<<<gg, 256>>>(x, Wo, bo, out, 3);
}

// round 5
// speedup vs baseline: 2.3681x; 1.2487x over previous
#include <cuda_runtime.h>

// Problem constants
#define B_TOT 512
#define N_TOK 145
#define M_TOK 144
#define C_DIM 512
#define H_NUM 8
#define HD    64
#define NWIN  4
#define ROWS  (B_TOT * N_TOK)                   // 74240
#define QKV_ELEMS (B_TOT * H_NUM * N_TOK * HD)  // 38,010,880

// Scratch (device globals; no allocation allowed)
__device__ float g_q[QKV_ELEMS];
__device__ float g_k[QKV_ELEMS];
__device__ float g_v[QKV_ELEMS];
__device__ float g_opre[ROWS * C_DIM];
__device__ float g_xt[ROWS * C_DIM];            // tf32-rounded x
__device__ float g_wt[4][C_DIM * C_DIM];        // tf32-rounded Wq,Wk,Wv,Wo
__device__ float g_comb[NWIN * H_NUM][N_TOK * N_TOK];  // mask + rpb fused

__device__ __forceinline__ float tf32f(float x) {
    unsigned r;
    asm("cvt.rna.tf32.f32 %0, %1;" : "=r"(r) : "f"(x));
    return __uint_as_float(r);
}

// ---------------------------------------------------------------------------
// Pre-conversion kernels
// ---------------------------------------------------------------------------
__global__ void cvt_x_kernel(const float* __restrict__ x) {
    int i = blockIdx.x * 256 + threadIdx.x;
    float4 v = ((const float4*)x)[i];
    v.x = tf32f(v.x); v.y = tf32f(v.y); v.z = tf32f(v.z); v.w = tf32f(v.w);
    ((float4*)g_xt)[i] = v;
}

__global__ void cvt_w_kernel(const float* __restrict__ w0,
                             const float* __restrict__ w1,
                             const float* __restrict__ w2,
                             const float* __restrict__ w3) {
    const float* src = (blockIdx.y == 0) ? w0 : (blockIdx.y == 1) ? w1
                     : (blockIdx.y == 2) ? w2 : w3;
    int i = blockIdx.x * 256 + threadIdx.x;
    float4 v = ((const float4*)src)[i];
    v.x = tf32f(v.x); v.y = tf32f(v.y); v.z = tf32f(v.z); v.w = tf32f(v.w);
    ((float4*)g_wt[blockIdx.y])[i] = v;
}

// Fused mask + relative-position-bias table: g_comb[w*8+h][i*145+j]
__global__ void comb_kernel(const float* __restrict__ mask,
                            const float* __restrict__ rpb) {
    int i = blockIdx.x, wh = blockIdx.y;
    int w = wh >> 3, h = wh & 7;
    int j = threadIdx.x;
    if (j >= N_TOK) return;
    float v = mask[(size_t)w * N_TOK * N_TOK + i * N_TOK + j];
    if (i < M_TOK && j < M_TOK) {
        int iH = i / 12, iW = i - iH * 12;
        int jH = j / 12, jW = j - jH * 12;
        int idx = (iH - jH + 11) * 23 + (iW - jW + 11);
        v += rpb[idx * H_NUM + h];
    }
    g_comb[wh][i * N_TOK + j] = v;
}

// ---------------------------------------------------------------------------
// TF32 tensor-core NT GEMM with cp.async 5-stage pipeline.
// out[m,n] = sum_k A[m,k]*W[n,k] + bias[n].  A,W pre-rounded to tf32.
// Block 128x128, 8 warps (2Mx4N), warp 64x32, mma.m16n8k8.
// smem per stage: A[128][16] + B[128][16] floats, element (m,k) at word
//   m*16 + (((k>>2) ^ ((m>>1)&3))<<2) + (k&3)
// -> cp.async 16B-aligned AND conflict-free fragment LDS (verified per-lane).
// ---------------------------------------------------------------------------
#define KC 16
#define NSTG (C_DIM / KC)   // 32
#define STAGES 5
#define STG_FLOATS 4096     // 2048 A + 2048 B
#define TGEMM_SMEM_BYTES (STAGES * STG_FLOATS * 4)   // 81920

__device__ __forceinline__ void cpasync16(unsigned saddr, const void* g) {
    asm volatile("cp.async.cg.shared.global [%0], [%1], 16;"
                 :: "r"(saddr), "l"(g) : "memory");
}

__device__ __forceinline__ void mma_tf32(float* d,
    unsigned a0, unsigned a1, unsigned a2, unsigned a3,
    unsigned b0, unsigned b1)
{
    asm volatile(
        "mma.sync.aligned.m16n8k8.row.col.f32.tf32.tf32.f32 "
        "{%0,%1,%2,%3}, {%4,%5,%6,%7}, {%8,%9}, {%0,%1,%2,%3};"
        : "+f"(d[0]), "+f"(d[1]), "+f"(d[2]), "+f"(d[3])
        : "r"(a0), "r"(a1), "r"(a2), "r"(a3), "r"(b0), "r"(b1));
}

__global__ void __launch_bounds__(256, 2) tgemm(
    const float* __restrict__ bias,
    float* __restrict__ outPlain,
    int sel)
{
    extern __shared__ float smd[];
    const float* A = (sel == 3) ? g_opre : g_xt;
    const float* W = g_wt[(sel == 3) ? 3 : sel];

    int tid = threadIdx.x;
    int lane = tid & 31, warp = tid >> 5;
    int wm = warp & 1, wn = warp >> 1;
    int m0 = blockIdx.y * 128, n0 = blockIdx.x * 128;

    const float* Ag = A + (size_t)m0 * C_DIM;
    const float* Wg = W + (size_t)n0 * C_DIM;
    unsigned sbase = (unsigned)__cvta_generic_to_shared(smd);

    // Per-thread cp.async mapping: 2 chunks per matrix per stage
    int chk0 = tid, chk1 = tid + 256;
    int cm0 = chk0 >> 2, cc0 = chk0 & 3;
    int cm1 = chk1 >> 2, cc1 = chk1 & 3;
    unsigned so0 = (unsigned)(cm0 * 16 + ((cc0 ^ ((cm0 >> 1) & 3)) << 2)) * 4u;
    unsigned so1 = (unsigned)(cm1 * 16 + ((cc1 ^ ((cm1 >> 1) & 3)) << 2)) * 4u;
    const float* ag0 = Ag + (size_t)cm0 * C_DIM + cc0 * 4;
    const float* ag1 = Ag + (size_t)cm1 * C_DIM + cc1 * 4;
    const float* wg0 = Wg + (size_t)cm0 * C_DIM + cc0 * 4;
    const float* wg1 = Wg + (size_t)cm1 * C_DIM + cc1 * 4;

    float acc[4][4][4];
#pragma unroll
    for (int mt = 0; mt < 4; mt++)
#pragma unroll
        for (int nt = 0; nt < 4; nt++)
#pragma unroll
            for (int i = 0; i < 4; i++) acc[mt][nt][i] = 0.f;

    // Prologue: issue stages 0..3
#pragma unroll
    for (int s = 0; s < 4; s++) {
        unsigned sb = sbase + (unsigned)(s * STG_FLOATS) * 4u;
        cpasync16(sb + so0, ag0 + s * KC);
        cpasync16(sb + so1, ag1 + s * KC);
        cpasync16(sb + 2048 * 4 + so0, wg0 + s * KC);
        cpasync16(sb + 2048 * 4 + so1, wg1 + s * KC);
        asm volatile("cp.async.commit_group;");
    }

    int c = lane & 3, lr = lane >> 2;

    for (int s = 0; s < NSTG; s++) {
        if (s < NSTG - 3)       asm volatile("cp.async.wait_group 3;");
        else if (s == NSTG - 3) asm volatile("cp.async.wait_group 2;");
        else if (s == NSTG - 2) asm volatile("cp.async.wait_group 1;");
        else                    asm volatile("cp.async.wait_group 0;");
        __syncthreads();

        if (s + 4 < NSTG) {
            int sn = s + 4;
            unsigned sb = sbase + (unsigned)((sn % STAGES) * STG_FLOATS) * 4u;
            cpasync16(sb + so0, ag0 + sn * KC);
            cpasync16(sb + so1, ag1 + sn * KC);
            cpasync16(sb + 2048 * 4 + so0, wg0 + sn * KC);
            cpasync16(sb + 2048 * 4 + so1, wg1 + sn * KC);
            asm volatile("cp.async.commit_group;");
        }

        float* As = smd + (s % STAGES) * STG_FLOATS;
        float* Bs = As + 2048;
#pragma unroll
        for (int ks = 0; ks < 2; ks++) {
            unsigned af[4][4], bf[4][2];
#pragma unroll
            for (int mt = 0; mt < 4; mt++) {
                int mr = wm * 64 + mt * 16 + lr;
                int mr2 = mr + 8;
                int s0 = ((2 * ks) ^ ((mr >> 1) & 3)) << 2;
                int s1 = ((2 * ks + 1) ^ ((mr >> 1) & 3)) << 2;
                af[mt][0] = __float_as_uint(As[mr * 16 + s0 + c]);
                af[mt][1] = __float_as_uint(As[mr2 * 16 + s0 + c]);
                af[mt][2] = __float_as_uint(As[mr * 16 + s1 + c]);
                af[mt][3] = __float_as_uint(As[mr2 * 16 + s1 + c]);
            }
#pragma unroll
            for (int nt = 0; nt < 4; nt++) {
                int nr = wn * 32 + nt * 8 + lr;
                int s0 = ((2 * ks) ^ ((nr >> 1) & 3)) << 2;
                int s1 = ((2 * ks + 1) ^ ((nr >> 1) & 3)) << 2;
                bf[nt][0] = __float_as_uint(Bs[nr * 16 + s0 + c]);
                bf[nt][1] = __float_as_uint(Bs[nr * 16 + s1 + c]);
            }
#pragma unroll
            for (int mt = 0; mt < 4; mt++)
#pragma unroll
                for (int nt = 0; nt < 4; nt++)
                    mma_tf32(acc[mt][nt], af[mt][0], af[mt][1], af[mt][2],
                             af[mt][3], bf[nt][0], bf[nt][1]);
        }
    }

    // Epilogue: bias add + scatter
    float* qkvbase = (sel == 0) ? g_q : (sel == 1) ? g_k : g_v;
#pragma unroll
    for (int mt = 0; mt < 4; mt++) {
#pragma unroll
        for (int half = 0; half < 2; half++) {
            int gm = m0 + wm * 64 + mt * 16 + lr + half * 8;
            int b_ = gm / N_TOK;
            int t  = gm - b_ * N_TOK;
#pragma unroll
            for (int nt = 0; nt < 4; nt++) {
                int gn = n0 + wn * 32 + nt * 8 + c * 2;
                float v0 = acc[mt][nt][half * 2 + 0] + bias[gn];
                float v1 = acc[mt][nt][half * 2 + 1] + bias[gn + 1];
                float* dst;
                if (sel == 3) {
                    dst = outPlain + (size_t)gm * C_DIM + gn;
                } else {
                    int h = gn >> 6, d = gn & 63;
                    dst = qkvbase +
                          ((((size_t)b_ * H_NUM + h) * N_TOK + t) * HD + d);
                }
                *(float2*)dst = make_float2(v0, v1);
            }
        }
    }
}

// ---------------------------------------------------------------------------
// Window attention: one block per (b_, h). Vectorized float4 paths.
// K in smem stride 68; V transposed [d][n] stride 148 (conflict-free LDS.128).
// Fused mask+bias from g_comb. Outputs stored tf32-rounded (final GEMM would
// round them anyway).
// ---------------------------------------------------------------------------
#define KS2 68
#define VTS 148
#define ATTN_SMEM_FLOATS (N_TOK * KS2 + HD * VTS + 1024 + 4 * 4 * VTS)
#define ATTN_SMEM_BYTES  (ATTN_SMEM_FLOATS * 4)

__global__ void __launch_bounds__(128) attn_kernel()
{
    extern __shared__ __align__(16) float sm[];
    float* Ks = sm;                       // 145*68 = 9860
    float* Vt = Ks + N_TOK * KS2;         // 64*148 = 9472
    float* Qs = Vt + HD * VTS;            // 1024
    float* Ps = Qs + 1024;                // 4*4*148

    int bh = blockIdx.x;
    int b_ = bh >> 3, h = bh & 7, w = b_ & 3;
    const float* gK = g_k + (size_t)bh * (N_TOK * HD);
    const float* gV = g_v + (size_t)bh * (N_TOK * HD);
    const float* gQ = g_q + (size_t)bh * (N_TOK * HD);
    const float* comb = g_comb[w * 8 + h];
    int tid = threadIdx.x, lane = tid & 31, warp = tid >> 5;

    // Stage K (vectorized) and V (transposed)
    {
        const float4* gK4 = (const float4*)gK;
        for (int i4 = tid; i4 < N_TOK * 16; i4 += 128) {
            int n = i4 >> 4, d4 = i4 & 15;
            *(float4*)(Ks + n * KS2 + d4 * 4) = gK4[i4];
        }
        for (int i = tid; i < N_TOK * HD; i += 128) {
            int n = i >> 6, d = i & 63;
            Vt[d * VTS + n] = gV[i];
        }
    }
    __syncthreads();

    float* Qw = Qs + warp * 256;
    float* Pw = Ps + warp * (4 * VTS);

    const float* kb[5];
#pragma unroll
    for (int jj = 0; jj < 5; jj++) {
        int j = lane + jj * 32;
        kb[jj] = Ks + ((j < N_TOK) ? j : 0) * KS2;
    }
    const float* vta = Vt + lane * VTS;
    const float* vtb = Vt + (lane + 32) * VTS;

    for (int iter = 0; iter < 9; iter++) {
        int row0 = iter * 16 + warp * 4;
        {
            const float4* gQ4 = (const float4*)(gQ + row0 * HD);
            ((float4*)Qw)[lane] = gQ4[lane];
            ((float4*)Qw)[lane + 32] = gQ4[lane + 32];
        }
        __syncwarp();

        float acc[4][5];
#pragma unroll
        for (int r = 0; r < 4; r++)
#pragma unroll
            for (int jj = 0; jj < 5; jj++) acc[r][jj] = 0.f;

#pragma unroll 4
        for (int d4 = 0; d4 < 16; d4++) {
            float4 q0 = *(const float4*)(Qw + d4 * 4);
            float4 q1 = *(const float4*)(Qw + 64 + d4 * 4);
            float4 q2 = *(const float4*)(Qw + 128 + d4 * 4);
            float4 q3 = *(const float4*)(Qw + 192 + d4 * 4);
#pragma unroll
            for (int jj = 0; jj < 5; jj++) {
                float4 kv = *(const float4*)(kb[jj] + d4 * 4);
                acc[0][jj] += q0.x * kv.x + q0.y * kv.y + q0.z * kv.z + q0.w * kv.w;
                acc[1][jj] += q1.x * kv.x + q1.y * kv.y + q1.z * kv.z + q1.w * kv.w;
                acc[2][jj] += q2.x * kv.x + q2.y * kv.y + q2.z * kv.z + q2.w * kv.w;
                acc[3][jj] += q3.x * kv.x + q3.y * kv.y + q3.z * kv.z + q3.w * kv.w;
            }
        }

#pragma unroll
        for (int r = 0; r < 4; r++) {
            int row = row0 + r;
            const float* crow = comb + row * N_TOK;
            float l[5];
#pragma unroll
            for (int jj = 0; jj < 5; jj++) {
                int j = lane + jj * 32;
                l[jj] = (j < N_TOK) ? (acc[r][jj] * 0.125f + crow[j]) : -1e30f;
            }
            float mx = l[0];
#pragma unroll
            for (int jj = 1; jj < 5; jj++) mx = fmaxf(mx, l[jj]);
#pragma unroll
            for (int o = 16; o > 0; o >>= 1)
                mx = fmaxf(mx, __shfl_xor_sync(0xffffffffu, mx, o));
            float s = 0.f;
#pragma unroll
            for (int jj = 0; jj < 5; jj++) {
                float e = __expf(l[jj] - mx);
                l[jj] = e;
                s += e;
            }
#pragma unroll
            for (int o = 16; o > 0; o >>= 1)
                s += __shfl_xor_sync(0xffffffffu, s, o);
            float inv = 1.f / s;
#pragma unroll
            for (int jj = 0; jj < 5; jj++) {
                int j = lane + jj * 32;
                if (j < N_TOK) Pw[r * VTS + j] = l[jj] * inv;
            }
        }
        __syncwarp();

        float o00 = 0.f, o01 = 0.f, o10 = 0.f, o11 = 0.f;
        float o20 = 0.f, o21 = 0.f, o30 = 0.f, o31 = 0.f;
#pragma unroll 4
        for (int k4 = 0; k4 < 36; k4++) {
            float4 va = *(const float4*)(vta + k4 * 4);
            float4 vb = *(const float4*)(vtb + k4 * 4);
            float4 p0 = *(const float4*)(Pw + k4 * 4);
            float4 p1 = *(const float4*)(Pw + VTS + k4 * 4);
            float4 p2 = *(const float4*)(Pw + 2 * VTS + k4 * 4);
            float4 p3 = *(const float4*)(Pw + 3 * VTS + k4 * 4);
            o00 += p0.x * va.x + p0.y * va.y + p0.z * va.z + p0.w * va.w;
            o01 += p0.x * vb.x + p0.y * vb.y + p0.z * vb.z + p0.w * vb.w;
            o10 += p1.x * va.x + p1.y * va.y + p1.z * va.z + p1.w * va.w;
            o11 += p1.x * vb.x + p1.y * vb.y + p1.z * vb.z + p1.w * vb.w;
            o20 += p2.x * va.x + p2.y * va.y + p2.z * va.z + p2.w * va.w;
            o21 += p2.x * vb.x + p2.y * vb.y + p2.z * vb.z + p2.w * vb.w;
            o30 += p3.x * va.x + p3.y * va.y + p3.z * va.z + p3.w * va.w;
            o31 += p3.x * vb.x + p3.y * vb.y + p3.z * vb.z + p3.w * vb.w;
        }
        {   // k = 144 remainder
            float va1 = vta[144], vb1 = vtb[144];
            float pa = Pw[144], pb = Pw[VTS + 144];
            float pc = Pw[2 * VTS + 144], pd = Pw[3 * VTS + 144];
            o00 += pa * va1; o01 += pa * vb1;
            o10 += pb * va1; o11 += pb * vb1;
            o20 += pc * va1; o21 += pc * vb1;
            o30 += pd * va1; o31 += pd * vb1;
        }
        {
            float* dst = g_opre + (size_t)(b_ * N_TOK + row0) * C_DIM + h * HD;
            dst[lane] = tf32f(o00); dst[lane + 32] = tf32f(o01); dst += C_DIM;
            dst[lane] = tf32f(o10); dst[lane + 32] = tf32f(o11); dst += C_DIM;
            dst[lane] = tf32f(o20); dst[lane + 32] = tf32f(o21); dst += C_DIM;
            dst[lane] = tf32f(o30); dst[lane + 32] = tf32f(o31);
        }
        __syncwarp();
    }
}

// ---------------------------------------------------------------------------
// Global-token redistribution: one block per (b, h).
// ---------------------------------------------------------------------------
__global__ void __launch_bounds__(128) gx_kernel(const float* __restrict__ mask)
{
    __shared__ __align__(16) float L[580];
    __shared__ __align__(16) float Qg[256];
    __shared__ __align__(16) float red[128];
    __shared__ float s_inv;

    int b = blockIdx.x >> 3, h = blockIdx.x & 7;
    int tid = threadIdx.x;

    for (int i = tid; i < 256; i += 128) {
        int w = i >> 6, d = i & 63;
        Qg[i] = g_q[(((size_t)(b * 4 + w) * H_NUM + h) * N_TOK + M_TOK) * HD + d];
    }
    __syncthreads();

    for (int idx = tid; idx < 577; idx += 128) {
        if (idx < 576) {
            int w = idx / 144, n = idx - w * 144;
            const float4* kp = (const float4*)(g_k +
                (((size_t)(b * 4 + w) * H_NUM + h) * N_TOK + n) * HD);
            const float4* qp = (const float4*)(Qg + w * 64);
            float dot = 0.f;
#pragma unroll
            for (int t = 0; t < 16; t++) {
                float4 kv = kp[t], qv = qp[t];
                dot += kv.x * qv.x + kv.y * qv.y + kv.z * qv.z + kv.w * qv.w;
            }
            L[idx] = dot * 0.125f +
                     mask[(size_t)w * (N_TOK * N_TOK) + M_TOK * N_TOK + n];
        } else {
            float s = 0.f;
            for (int w = 0; w < 4; w++) {
                const float4* kp = (const float4*)(g_k +
                    (((size_t)(b * 4 + w) * H_NUM + h) * N_TOK + M_TOK) * HD);
                const float4* qp = (const float4*)(Qg + w * 64);
                float dot = 0.f;
#pragma unroll
                for (int t = 0; t < 16; t++) {
                    float4 kv = kp[t], qv = qp[t];
                    dot += kv.x * qv.x + kv.y * qv.y + kv.z * qv.z + kv.w * qv.w;
                }
                s += dot * 0.125f +
                     mask[(size_t)w * (N_TOK * N_TOK) + M_TOK * N_TOK + M_TOK];
            }
            L[576] = s * 0.25f;
        }
    }
    __syncthreads();

    float mx = -1e30f;
    for (int idx = tid; idx < 577; idx += 128) mx = fmaxf(mx, L[idx]);
    red[tid] = mx;
    __syncthreads();
    for (int s2 = 64; s2 > 0; s2 >>= 1) {
        if (tid < s2) red[tid] = fmaxf(red[tid], red[tid + s2]);
        __syncthreads();
    }
    mx = red[0];
    __syncthreads();

    float ps = 0.f;
    for (int idx = tid; idx < 577; idx += 128) {
        float e = __expf(L[idx] - mx);
        L[idx] = e;
        ps += e;
    }
    red[tid] = ps;
    __syncthreads();
    for (int s2 = 64; s2 > 0; s2 >>= 1) {
        if (tid < s2) red[tid] += red[tid + s2];
        __syncthreads();
    }
    if (tid == 0) s_inv = 1.f / red[0];
    __syncthreads();

    int d = tid & 63, half = tid >> 6;
    float acc = 0.f;
    for (int w = 0; w < 4; w++) {
        const float* vb = g_v + (((size_t)(b * 4 + w) * H_NUM + h) * N_TOK) * HD;
        for (int n = half; n < M_TOK; n += 2)
            acc += L[w * 144 + n] * vb[n * HD + d];
        if ((w & 1) == half)
            acc += L[576] * vb[M_TOK * HD + d];
    }
    red[tid] = acc;
    __syncthreads();
    if (half == 0) {
        float tot = tf32f((red[tid] + red[tid + 64]) * s_inv);
#pragma unroll
        for (int w = 0; w < 4; w++)
            g_opre[(size_t)((b * 4 + w) * N_TOK + M_TOK) * C_DIM + h * HD + d] = tot;
    }
}

// ---------------------------------------------------------------------------
extern "C" void kernel_launch(void* const* d_in, const int* in_sizes, int n_in,
                              void* d_out, int out_size)
{
    const float* x    = (const float*)d_in[0];
    const float* mask = (const float*)d_in[1];
    const float* rpb  = (const float*)d_in[2];
    const float* Wq   = (const float*)d_in[3];
    const float* bq   = (const float*)d_in[4];
    const float* Wk   = (const float*)d_in[5];
    const float* bk   = (const float*)d_in[6];
    const float* Wv   = (const float*)d_in[7];
    const float* bv   = (const float*)d_in[8];
    const float* Wo   = (const float*)d_in[9];
    const float* bo   = (const float*)d_in[10];
    float* out = (float*)d_out;

    cudaFuncSetAttribute(tgemm, cudaFuncAttributeMaxDynamicSharedMemorySize,
                         TGEMM_SMEM_BYTES);
    cudaFuncSetAttribute(attn_kernel, cudaFuncAttributeMaxDynamicSharedMemorySize,
                         ATTN_SMEM_BYTES);

    cvt_x_kernel<<<ROWS * C_DIM / 1024, 256>>>(x);
    cvt_w_kernel<<<dim3(C_DIM * C_DIM / 1024, 4), 256>>>(Wq, Wk, Wv, Wo);
    comb_kernel<<<dim3(N_TOK, NWIN * H_NUM), 160>>>(mask, rpb);

    dim3 gg(4, 580, 1);   // 512/128 x 74240/128
    tgemm<<<gg, 256, TGEMM_SMEM_BYTES>>>(bq, nullptr, 0);
    tgemm<<<gg, 256, TGEMM_SMEM_BYTES>>>(bk, nullptr, 1);
    tgemm<<<gg, 256, TGEMM_SMEM_BYTES>>>(bv, nullptr, 2);

    attn_kernel<<<4096, 128, ATTN_SMEM_BYTES>>>();
    gx_kernel<<<1024, 128>>>(mask);

    tgemm<<<gg, 256, TGEMM_SMEM_BYTES>>>(bo, out, 3);
}

// round 6
// speedup vs baseline: 2.5495x; 1.0766x over previous
#include <cuda_runtime.h>

// Problem constants
#define B_TOT 512
#define N_TOK 145
#define M_TOK 144
#define C_DIM 512
#define H_NUM 8
#define HD    64
#define NWIN  4
#define ROWS  (B_TOT * N_TOK)                   // 74240
#define QKV_ELEMS (B_TOT * H_NUM * N_TOK * HD)  // 38,010,880

// Scratch (device globals; no allocation allowed)
__device__ float g_q[QKV_ELEMS];
__device__ float g_k[QKV_ELEMS];
__device__ float g_v[QKV_ELEMS];
__device__ float g_opre[ROWS * C_DIM];
__device__ float g_xt[ROWS * C_DIM];            // tf32-rounded x
__device__ float g_wt[4][C_DIM * C_DIM];        // tf32-rounded Wq,Wk,Wv,Wo
__device__ float g_comb[NWIN * H_NUM][N_TOK * N_TOK];  // mask + rpb fused

__device__ __forceinline__ float tf32f(float x) {
    unsigned r;
    asm("cvt.rna.tf32.f32 %0, %1;" : "=r"(r) : "f"(x));
    return __uint_as_float(r);
}

// ---------------------------------------------------------------------------
// Pre-conversion kernels
// ---------------------------------------------------------------------------
__global__ void cvt_x_kernel(const float* __restrict__ x) {
    int i = blockIdx.x * 256 + threadIdx.x;
    float4 v = ((const float4*)x)[i];
    v.x = tf32f(v.x); v.y = tf32f(v.y); v.z = tf32f(v.z); v.w = tf32f(v.w);
    ((float4*)g_xt)[i] = v;
}

__global__ void cvt_w_kernel(const float* __restrict__ w0,
                             const float* __restrict__ w1,
                             const float* __restrict__ w2,
                             const float* __restrict__ w3) {
    const float* src = (blockIdx.y == 0) ? w0 : (blockIdx.y == 1) ? w1
                     : (blockIdx.y == 2) ? w2 : w3;
    int i = blockIdx.x * 256 + threadIdx.x;
    float4 v = ((const float4*)src)[i];
    v.x = tf32f(v.x); v.y = tf32f(v.y); v.z = tf32f(v.z); v.w = tf32f(v.w);
    ((float4*)g_wt[blockIdx.y])[i] = v;
}

// Fused mask + relative-position-bias table: g_comb[w*8+h][i*145+j]
__global__ void comb_kernel(const float* __restrict__ mask,
                            const float* __restrict__ rpb) {
    int i = blockIdx.x, wh = blockIdx.y;
    int w = wh >> 3, h = wh & 7;
    int j = threadIdx.x;
    if (j >= N_TOK) return;
    float v = mask[(size_t)w * N_TOK * N_TOK + i * N_TOK + j];
    if (i < M_TOK && j < M_TOK) {
        int iH = i / 12, iW = i - iH * 12;
        int jH = j / 12, jW = j - jH * 12;
        int idx = (iH - jH + 11) * 23 + (iW - jW + 11);
        v += rpb[idx * H_NUM + h];
    }
    g_comb[wh][i * N_TOK + j] = v;
}

// ---------------------------------------------------------------------------
// TF32 tensor-core NT GEMM, cp.async 5-stage pipeline + ldmatrix fragments.
// out[m,n] = sum_k A[m,k]*W[n,k] + bias[n].  A,W pre-rounded to tf32.
// Block 128x128, 8 warps (2Mx4N), warp 64x32, mma.m16n8k8.
// smem per stage: element (m,k) at word  m*16 + (((k>>2)^((m>>1)&3))<<2)+(k&3)
// -> cp.async 16B-aligned, conflict-free ldmatrix (8 row-segments per phase
//    hit bank-groups {0..3}^kg and {4..7}^kg — all distinct; verified).
// ---------------------------------------------------------------------------
#define KC 16
#define NSTG (C_DIM / KC)   // 32
#define STAGES 5
#define STG_FLOATS 4096     // 2048 A + 2048 B
#define TGEMM_SMEM_BYTES (STAGES * STG_FLOATS * 4)   // 81920

__device__ __forceinline__ void cpasync16(unsigned saddr, const void* g) {
    asm volatile("cp.async.cg.shared.global [%0], [%1], 16;"
                 :: "r"(saddr), "l"(g) : "memory");
}

__device__ __forceinline__ void ldsm4(unsigned* r, unsigned addr) {
    asm volatile("ldmatrix.sync.aligned.m8n8.x4.shared.b16 {%0,%1,%2,%3}, [%4];"
                 : "=r"(r[0]), "=r"(r[1]), "=r"(r[2]), "=r"(r[3]) : "r"(addr));
}

__device__ __forceinline__ void mma_tf32(float* d,
    unsigned a0, unsigned a1, unsigned a2, unsigned a3,
    unsigned b0, unsigned b1)
{
    asm volatile(
        "mma.sync.aligned.m16n8k8.row.col.f32.tf32.tf32.f32 "
        "{%0,%1,%2,%3}, {%4,%5,%6,%7}, {%8,%9}, {%0,%1,%2,%3};"
        : "+f"(d[0]), "+f"(d[1]), "+f"(d[2]), "+f"(d[3])
        : "r"(a0), "r"(a1), "r"(a2), "r"(a3), "r"(b0), "r"(b1));
}

__global__ void __launch_bounds__(256, 2) tgemm(
    const float* __restrict__ bias,
    float* __restrict__ outPlain,
    int sel)
{
    extern __shared__ float smd[];
    const float* A = (sel == 3) ? g_opre : g_xt;
    const float* W = g_wt[(sel == 3) ? 3 : sel];

    int tid = threadIdx.x;
    int lane = tid & 31, warp = tid >> 5;
    int wm = warp & 1, wn = warp >> 1;
    int m0 = blockIdx.y * 128, n0 = blockIdx.x * 128;

    const float* Ag = A + (size_t)m0 * C_DIM;
    const float* Wg = W + (size_t)n0 * C_DIM;
    unsigned sbase = (unsigned)__cvta_generic_to_shared(smd);

    // cp.async mapping: 2 chunks per matrix per stage per thread
    int chk0 = tid, chk1 = tid + 256;
    int cm0 = chk0 >> 2, cc0 = chk0 & 3;
    int cm1 = chk1 >> 2, cc1 = chk1 & 3;
    unsigned so0 = (unsigned)(cm0 * 16 + ((cc0 ^ ((cm0 >> 1) & 3)) << 2)) * 4u;
    unsigned so1 = (unsigned)(cm1 * 16 + ((cc1 ^ ((cm1 >> 1) & 3)) << 2)) * 4u;
    const float* ag0 = Ag + (size_t)cm0 * C_DIM + cc0 * 4;
    const float* ag1 = Ag + (size_t)cm1 * C_DIM + cc1 * 4;
    const float* wg0 = Wg + (size_t)cm0 * C_DIM + cc0 * 4;
    const float* wg1 = Wg + (size_t)cm1 * C_DIM + cc1 * 4;

    // ldmatrix per-lane addressing
    int lr8 = lane & 7;
    int tq  = lane >> 3;            // tile quadrant 0..3
    unsigned aoff[4]; int akey[4];
#pragma unroll
    for (int mt = 0; mt < 4; mt++) {
        int arow = wm * 64 + mt * 16 + ((tq & 1) << 3) + lr8;
        aoff[mt] = (unsigned)(arow * 16);
        akey[mt] = (arow >> 1) & 3;
    }
    int akgh = tq >> 1;
    unsigned boff[2]; int bkey[2];
#pragma unroll
    for (int p = 0; p < 2; p++) {
        int brow = wn * 32 + p * 16 + ((lane >> 4) << 3) + lr8;
        boff[p] = (unsigned)(brow * 16);
        bkey[p] = (brow >> 1) & 3;
    }
    int bkgh = tq & 1;

    float acc[4][4][4];
#pragma unroll
    for (int mt = 0; mt < 4; mt++)
#pragma unroll
        for (int nt = 0; nt < 4; nt++)
#pragma unroll
            for (int i = 0; i < 4; i++) acc[mt][nt][i] = 0.f;

    // Prologue: issue stages 0..3
#pragma unroll
    for (int s = 0; s < 4; s++) {
        unsigned sb = sbase + (unsigned)(s * STG_FLOATS) * 4u;
        cpasync16(sb + so0, ag0 + s * KC);
        cpasync16(sb + so1, ag1 + s * KC);
        cpasync16(sb + 2048 * 4 + so0, wg0 + s * KC);
        cpasync16(sb + 2048 * 4 + so1, wg1 + s * KC);
        asm volatile("cp.async.commit_group;");
    }

    int c = lane & 3, lr = lane >> 2;
    (void)c; (void)lr;

    for (int s = 0; s < NSTG; s++) {
        if (s < NSTG - 3)       asm volatile("cp.async.wait_group 3;");
        else if (s == NSTG - 3) asm volatile("cp.async.wait_group 2;");
        else if (s == NSTG - 2) asm volatile("cp.async.wait_group 1;");
        else                    asm volatile("cp.async.wait_group 0;");
        __syncthreads();

        if (s + 4 < NSTG) {
            int sn = s + 4;
            unsigned sb = sbase + (unsigned)((sn % STAGES) * STG_FLOATS) * 4u;
            cpasync16(sb + so0, ag0 + sn * KC);
            cpasync16(sb + so1, ag1 + sn * KC);
            cpasync16(sb + 2048 * 4 + so0, wg0 + sn * KC);
            cpasync16(sb + 2048 * 4 + so1, wg1 + sn * KC);
            asm volatile("cp.async.commit_group;");
        }

        unsigned stw = sbase + (unsigned)((s % STAGES) * STG_FLOATS) * 4u;
#pragma unroll
        for (int ks = 0; ks < 2; ks++) {
            unsigned af[4][4], bq2[2][4];
#pragma unroll
            for (int mt = 0; mt < 4; mt++) {
                int kg = 2 * ks + akgh;
                unsigned ad = stw + (aoff[mt] + (unsigned)((kg ^ akey[mt]) << 2)) * 4u;
                ldsm4(af[mt], ad);
            }
#pragma unroll
            for (int p = 0; p < 2; p++) {
                int kg = 2 * ks + bkgh;
                unsigned bd = stw + 2048 * 4u +
                              (boff[p] + (unsigned)((kg ^ bkey[p]) << 2)) * 4u;
                ldsm4(bq2[p], bd);
            }
#pragma unroll
            for (int mt = 0; mt < 4; mt++)
#pragma unroll
                for (int nt = 0; nt < 4; nt++) {
                    int p = nt >> 1, o = (nt & 1) * 2;
                    mma_tf32(acc[mt][nt], af[mt][0], af[mt][1], af[mt][2],
                             af[mt][3], bq2[p][o], bq2[p][o + 1]);
                }
        }
    }

    // Epilogue: bias add + scatter
    float* qkvbase = (sel == 0) ? g_q : (sel == 1) ? g_k : g_v;
    int cc = lane & 3, lrr = lane >> 2;
#pragma unroll
    for (int mt = 0; mt < 4; mt++) {
#pragma unroll
        for (int half = 0; half < 2; half++) {
            int gm = m0 + wm * 64 + mt * 16 + lrr + half * 8;
            int b_ = gm / N_TOK;
            int t  = gm - b_ * N_TOK;
#pragma unroll
            for (int nt = 0; nt < 4; nt++) {
                int gn = n0 + wn * 32 + nt * 8 + cc * 2;
                float v0 = acc[mt][nt][half * 2 + 0] + bias[gn];
                float v1 = acc[mt][nt][half * 2 + 1] + bias[gn + 1];
                float* dst;
                if (sel == 3) {
                    dst = outPlain + (size_t)gm * C_DIM + gn;
                } else {
                    int h = gn >> 6, d = gn & 63;
                    dst = qkvbase +
                          ((((size_t)b_ * H_NUM + h) * N_TOK + t) * HD + d);
                }
                *(float2*)dst = make_float2(v0, v1);
            }
        }
    }
}

// ---------------------------------------------------------------------------
// Window attention: one block per (b_, h), 256 threads (8 warps x 2 rows/iter).
// K in smem stride 68; V transposed [d][n] stride 148; fused mask+bias table.
// ---------------------------------------------------------------------------
#define KS2 68
#define VTS 148
#define ATTN_SMEM_FLOATS (N_TOK * KS2 + HD * VTS + 1024 + 8 * 2 * VTS)
#define ATTN_SMEM_BYTES  (ATTN_SMEM_FLOATS * 4)

__global__ void __launch_bounds__(256) attn_kernel()
{
    extern __shared__ __align__(16) float sm[];
    float* Ks = sm;                       // 145*68 = 9860
    float* Vt = Ks + N_TOK * KS2;         // 64*148 = 9472
    float* Qs = Vt + HD * VTS;            // 8 warps * 128
    float* Ps = Qs + 1024;                // 8 warps * 2 * 148

    int bh = blockIdx.x;
    int b_ = bh >> 3, h = bh & 7, w = b_ & 3;
    const float* gK = g_k + (size_t)bh * (N_TOK * HD);
    const float* gV = g_v + (size_t)bh * (N_TOK * HD);
    const float* gQ = g_q + (size_t)bh * (N_TOK * HD);
    const float* comb = g_comb[w * 8 + h];
    int tid = threadIdx.x, lane = tid & 31, warp = tid >> 5;

    // Stage K (vectorized) and V (transposed)
    {
        const float4* gK4 = (const float4*)gK;
        for (int i4 = tid; i4 < N_TOK * 16; i4 += 256) {
            int n = i4 >> 4, d4 = i4 & 15;
            *(float4*)(Ks + n * KS2 + d4 * 4) = gK4[i4];
        }
        for (int i = tid; i < N_TOK * HD; i += 256) {
            int n = i >> 6, d = i & 63;
            Vt[d * VTS + n] = gV[i];
        }
    }
    __syncthreads();

    float* Qw = Qs + warp * 128;
    float* Pw = Ps + warp * (2 * VTS);

    const float* kb[5];
#pragma unroll
    for (int jj = 0; jj < 5; jj++) {
        int j = lane + jj * 32;
        kb[jj] = Ks + ((j < N_TOK) ? j : 0) * KS2;
    }
    const float* vta = Vt + lane * VTS;
    const float* vtb = Vt + (lane + 32) * VTS;

    for (int iter = 0; iter < 9; iter++) {
        int row0 = iter * 16 + warp * 2;
        {
            const float4* gQ4 = (const float4*)(gQ + row0 * HD);
            ((float4*)Qw)[lane] = gQ4[lane];   // 2 rows = 32 float4
        }
        __syncwarp();

        float acc[2][5];
#pragma unroll
        for (int r = 0; r < 2; r++)
#pragma unroll
            for (int jj = 0; jj < 5; jj++) acc[r][jj] = 0.f;

#pragma unroll 4
        for (int d4 = 0; d4 < 16; d4++) {
            float4 q0 = *(const float4*)(Qw + d4 * 4);
            float4 q1 = *(const float4*)(Qw + 64 + d4 * 4);
#pragma unroll
            for (int jj = 0; jj < 5; jj++) {
                float4 kv = *(const float4*)(kb[jj] + d4 * 4);
                acc[0][jj] += q0.x * kv.x + q0.y * kv.y + q0.z * kv.z + q0.w * kv.w;
                acc[1][jj] += q1.x * kv.x + q1.y * kv.y + q1.z * kv.z + q1.w * kv.w;
            }
        }

#pragma unroll
        for (int r = 0; r < 2; r++) {
            int row = row0 + r;
            const float* crow = comb + row * N_TOK;
            float l[5];
#pragma unroll
            for (int jj = 0; jj < 5; jj++) {
                int j = lane + jj * 32;
                l[jj] = (j < N_TOK) ? (acc[r][jj] * 0.125f + crow[j]) : -1e30f;
            }
            float mx = l[0];
#pragma unroll
            for (int jj = 1; jj < 5; jj++) mx = fmaxf(mx, l[jj]);
#pragma unroll
            for (int o = 16; o > 0; o >>= 1)
                mx = fmaxf(mx, __shfl_xor_sync(0xffffffffu, mx, o));
            float s = 0.f;
#pragma unroll
            for (int jj = 0; jj < 5; jj++) {
                float e = __expf(l[jj] - mx);
                l[jj] = e;
                s += e;
            }
#pragma unroll
            for (int o = 16; o > 0; o >>= 1)
                s += __shfl_xor_sync(0xffffffffu, s, o);
            float inv = 1.f / s;
#pragma unroll
            for (int jj = 0; jj < 5; jj++) {
                int j = lane + jj * 32;
                if (j < N_TOK) Pw[r * VTS + j] = l[jj] * inv;
            }
        }
        __syncwarp();

        float o00 = 0.f, o01 = 0.f, o10 = 0.f, o11 = 0.f;
#pragma unroll 6
        for (int k4 = 0; k4 < 36; k4++) {
            float4 va = *(const float4*)(vta + k4 * 4);
            float4 vb = *(const float4*)(vtb + k4 * 4);
            float4 p0 = *(const float4*)(Pw + k4 * 4);
            float4 p1 = *(const float4*)(Pw + VTS + k4 * 4);
            o00 += p0.x * va.x + p0.y * va.y + p0.z * va.z + p0.w * va.w;
            o01 += p0.x * vb.x + p0.y * vb.y + p0.z * vb.z + p0.w * vb.w;
            o10 += p1.x * va.x + p1.y * va.y + p1.z * va.z + p1.w * va.w;
            o11 += p1.x * vb.x + p1.y * vb.y + p1.z * vb.z + p1.w * vb.w;
        }
        {   // k = 144 remainder
            float va1 = vta[144], vb1 = vtb[144];
            float pa = Pw[144], pb = Pw[VTS + 144];
            o00 += pa * va1; o01 += pa * vb1;
            o10 += pb * va1; o11 += pb * vb1;
        }
        {
            float* dst = g_opre + (size_t)(b_ * N_TOK + row0) * C_DIM + h * HD;
            dst[lane] = tf32f(o00); dst[lane + 32] = tf32f(o01); dst += C_DIM;
            dst[lane] = tf32f(o10); dst[lane + 32] = tf32f(o11);
        }
        __syncwarp();
    }
}

// ---------------------------------------------------------------------------
// Global-token redistribution: one block per (b, h).
// ---------------------------------------------------------------------------
__global__ void __launch_bounds__(128) gx_kernel(const float* __restrict__ mask)
{
    __shared__ __align__(16) float L[580];
    __shared__ __align__(16) float Qg[256];
    __shared__ __align__(16) float red[128];
    __shared__ float s_inv;

    int b = blockIdx.x >> 3, h = blockIdx.x & 7;
    int tid = threadIdx.x;

    for (int i = tid; i < 256; i += 128) {
        int w = i >> 6, d = i & 63;
        Qg[i] = g_q[(((size_t)(b * 4 + w) * H_NUM + h) * N_TOK + M_TOK) * HD + d];
    }
    __syncthreads();

    for (int idx = tid; idx < 577; idx += 128) {
        if (idx < 576) {
            int w = idx / 144, n = idx - w * 144;
            const float4* kp = (const float4*)(g_k +
                (((size_t)(b * 4 + w) * H_NUM + h) * N_TOK + n) * HD);
            const float4* qp = (const float4*)(Qg + w * 64);
            float dot = 0.f;
#pragma unroll
            for (int t = 0; t < 16; t++) {
                float4 kv = kp[t], qv = qp[t];
                dot += kv.x * qv.x + kv.y * qv.y + kv.z * qv.z + kv.w * qv.w;
            }
            L[idx] = dot * 0.125f +
                     mask[(size_t)w * (N_TOK * N_TOK) + M_TOK * N_TOK + n];
        } else {
            float s = 0.f;
            for (int w = 0; w < 4; w++) {
                const float4* kp = (const float4*)(g_k +
                    (((size_t)(b * 4 + w) * H_NUM + h) * N_TOK + M_TOK) * HD);
                const float4* qp = (const float4*)(Qg + w * 64);
                float dot = 0.f;
#pragma unroll
                for (int t = 0; t < 16; t++) {
                    float4 kv = kp[t], qv = qp[t];
                    dot += kv.x * qv.x + kv.y * qv.y + kv.z * qv.z + kv.w * qv.w;
                }
                s += dot * 0.125f +
                     mask[(size_t)w * (N_TOK * N_TOK) + M_TOK * N_TOK + M_TOK];
            }
            L[576] = s * 0.25f;
        }
    }
    __syncthreads();

    float mx = -1e30f;
    for (int idx = tid; idx < 577; idx += 128) mx = fmaxf(mx, L[idx]);
    red[tid] = mx;
    __syncthreads();
    for (int s2 = 64; s2 > 0; s2 >>= 1) {
        if (tid < s2) red[tid] = fmaxf(red[tid], red[tid + s2]);
        __syncthreads();
    }
    mx = red[0];
    __syncthreads();

    float ps = 0.f;
    for (int idx = tid; idx < 577; idx += 128) {
        float e = __expf(L[idx] - mx);
        L[idx] = e;
        ps += e;
    }
    red[tid] = ps;
    __syncthreads();
    for (int s2 = 64; s2 > 0; s2 >>= 1) {
        if (tid < s2) red[tid] += red[tid + s2];
        __syncthreads();
    }
    if (tid == 0) s_inv = 1.f / red[0];
    __syncthreads();

    int d = tid & 63, half = tid >> 6;
    float acc = 0.f;
    for (int w = 0; w < 4; w++) {
        const float* vb = g_v + (((size_t)(b * 4 + w) * H_NUM + h) * N_TOK) * HD;
        for (int n = half; n < M_TOK; n += 2)
            acc += L[w * 144 + n] * vb[n * HD + d];
        if ((w & 1) == half)
            acc += L[576] * vb[M_TOK * HD + d];
    }
    red[tid] = acc;
    __syncthreads();
    if (half == 0) {
        float tot = tf32f((red[tid] + red[tid + 64]) * s_inv);
#pragma unroll
        for (int w = 0; w < 4; w++)
            g_opre[(size_t)((b * 4 + w) * N_TOK + M_TOK) * C_DIM + h * HD + d] = tot;
    }
}

// ---------------------------------------------------------------------------
extern "C" void kernel_launch(void* const* d_in, const int* in_sizes, int n_in,
                              void* d_out, int out_size)
{
    const float* x    = (const float*)d_in[0];
    const float* mask = (const float*)d_in[1];
    const float* rpb  = (const float*)d_in[2];
    const float* Wq   = (const float*)d_in[3];
    const float* bq   = (const float*)d_in[4];
    const float* Wk   = (const float*)d_in[5];
    const float* bk   = (const float*)d_in[6];
    const float* Wv   = (const float*)d_in[7];
    const float* bv   = (const float*)d_in[8];
    const float* Wo   = (const float*)d_in[9];
    const float* bo   = (const float*)d_in[10];
    float* out = (float*)d_out;

    cudaFuncSetAttribute(tgemm, cudaFuncAttributeMaxDynamicSharedMemorySize,
                         TGEMM_SMEM_BYTES);
    cudaFuncSetAttribute(attn_kernel, cudaFuncAttributeMaxDynamicSharedMemorySize,
                         ATTN_SMEM_BYTES);

    cvt_x_kernel<<<ROWS * C_DIM / 1024, 256>>>(x);
    cvt_w_kernel<<<dim3(C_DIM * C_DIM / 1024, 4), 256>>>(Wq, Wk, Wv, Wo);
    comb_kernel<<<dim3(N_TOK, NWIN * H_NUM), 160>>>(mask, rpb);

    dim3 gg(4, 580, 1);   // 512/128 x 74240/128
    tgemm<<<gg, 256, TGEMM_SMEM_BYTES>>>(bq, nullptr, 0);
    tgemm<<<gg, 256, TGEMM_SMEM_BYTES>>>(bk, nullptr, 1);
    tgemm<<<gg, 256, TGEMM_SMEM_BYTES>>>(bv, nullptr, 2);

    attn_kernel<<<4096, 256, ATTN_SMEM_BYTES>>>();
    gx_kernel<<<1024, 128>>>(mask);

    tgemm<<<gg, 256, TGEMM_SMEM_BYTES>>>(bo, out, 3);
}

// round 8
// speedup vs baseline: 3.3202x; 1.3023x over previous
#include <cuda_runtime.h>

// Problem constants
#define B_TOT 512
#define N_TOK 145
#define M_TOK 144
#define C_DIM 512
#define H_NUM 8
#define HD    64
#define NWIN  4
#define ROWS  (B_TOT * N_TOK)                   // 74240
#define QKV_ELEMS (B_TOT * H_NUM * N_TOK * HD)  // 38,010,880

// Scratch (device globals; no allocation allowed)
__device__ float g_q[QKV_ELEMS];
__device__ float g_k[QKV_ELEMS];
__device__ float g_v[QKV_ELEMS];
__device__ float g_opre[ROWS * C_DIM];
__device__ float g_xt[ROWS * C_DIM];            // tf32-rounded x
__device__ float g_wt[4][C_DIM * C_DIM];        // tf32-rounded Wq,Wk,Wv,Wo
__device__ float g_comb[NWIN * H_NUM][N_TOK * 152];  // mask+rpb, stride 152, -inf pad

__device__ __forceinline__ float tf32f(float x) {
    unsigned r;
    asm("cvt.rna.tf32.f32 %0, %1;" : "=r"(r) : "f"(x));
    return __uint_as_float(r);
}

// ---------------------------------------------------------------------------
// Pre-conversion kernels
// ---------------------------------------------------------------------------
__global__ void cvt_x_kernel(const float* __restrict__ x) {
    int i = blockIdx.x * 256 + threadIdx.x;
    float4 v = ((const float4*)x)[i];
    v.x = tf32f(v.x); v.y = tf32f(v.y); v.z = tf32f(v.z); v.w = tf32f(v.w);
    ((float4*)g_xt)[i] = v;
}

__global__ void cvt_w_kernel(const float* __restrict__ w0,
                             const float* __restrict__ w1,
                             const float* __restrict__ w2,
                             const float* __restrict__ w3) {
    const float* src = (blockIdx.y == 0) ? w0 : (blockIdx.y == 1) ? w1
                     : (blockIdx.y == 2) ? w2 : w3;
    int i = blockIdx.x * 256 + threadIdx.x;
    float4 v = ((const float4*)src)[i];
    v.x = tf32f(v.x); v.y = tf32f(v.y); v.z = tf32f(v.z); v.w = tf32f(v.w);
    ((float4*)g_wt[blockIdx.y])[i] = v;
}

// Fused mask + rpb, stride 152, cols >=145 filled with -1e30 (auto-mask)
__global__ void comb_kernel(const float* __restrict__ mask,
                            const float* __restrict__ rpb) {
    int i = blockIdx.x, wh = blockIdx.y;
    int w = wh >> 3, h = wh & 7;
    int j = threadIdx.x;
    if (j >= 152) return;
    float v;
    if (j < N_TOK) {
        v = mask[(size_t)w * N_TOK * N_TOK + i * N_TOK + j];
        if (i < M_TOK && j < M_TOK) {
            int iH = i / 12, iW = i - iH * 12;
            int jH = j / 12, jW = j - jH * 12;
            int idx = (iH - jH + 11) * 23 + (iW - jW + 11);
            v += rpb[idx * H_NUM + h];
        }
    } else {
        v = -1e30f;
    }
    g_comb[wh][i * 152 + j] = v;
}

// ---------------------------------------------------------------------------
// Common mma helpers
// ---------------------------------------------------------------------------
__device__ __forceinline__ void cpasync16(unsigned saddr, const void* g) {
    asm volatile("cp.async.cg.shared.global [%0], [%1], 16;"
                 :: "r"(saddr), "l"(g) : "memory");
}

__device__ __forceinline__ void ldsm4(unsigned* r, unsigned addr) {
    asm volatile("ldmatrix.sync.aligned.m8n8.x4.shared.b16 {%0,%1,%2,%3}, [%4];"
                 : "=r"(r[0]), "=r"(r[1]), "=r"(r[2]), "=r"(r[3]) : "r"(addr));
}

__device__ __forceinline__ void mma_tf32(float* d,
    unsigned a0, unsigned a1, unsigned a2, unsigned a3,
    unsigned b0, unsigned b1)
{
    asm volatile(
        "mma.sync.aligned.m16n8k8.row.col.f32.tf32.tf32.f32 "
        "{%0,%1,%2,%3}, {%4,%5,%6,%7}, {%8,%9}, {%0,%1,%2,%3};"
        : "+f"(d[0]), "+f"(d[1]), "+f"(d[2]), "+f"(d[3])
        : "r"(a0), "r"(a1), "r"(a2), "r"(a3), "r"(b0), "r"(b1));
}

// ---------------------------------------------------------------------------
// TF32 tensor-core NT GEMM, cp.async 5-stage pipeline + ldmatrix fragments.
// (unchanged from R6)
// ---------------------------------------------------------------------------
#define KC 16
#define NSTG (C_DIM / KC)   // 32
#define STAGES 5
#define STG_FLOATS 4096     // 2048 A + 2048 B
#define TGEMM_SMEM_BYTES (STAGES * STG_FLOATS * 4)   // 81920

__global__ void __launch_bounds__(256, 2) tgemm(
    const float* __restrict__ bias,
    float* __restrict__ outPlain,
    int sel)
{
    extern __shared__ float smd[];
    const float* A = (sel == 3) ? g_opre : g_xt;
    const float* W = g_wt[(sel == 3) ? 3 : sel];

    int tid = threadIdx.x;
    int lane = tid & 31, warp = tid >> 5;
    int wm = warp & 1, wn = warp >> 1;
    int m0 = blockIdx.y * 128, n0 = blockIdx.x * 128;

    const float* Ag = A + (size_t)m0 * C_DIM;
    const float* Wg = W + (size_t)n0 * C_DIM;
    unsigned sbase = (unsigned)__cvta_generic_to_shared(smd);

    int chk0 = tid, chk1 = tid + 256;
    int cm0 = chk0 >> 2, cc0 = chk0 & 3;
    int cm1 = chk1 >> 2, cc1 = chk1 & 3;
    unsigned so0 = (unsigned)(cm0 * 16 + ((cc0 ^ ((cm0 >> 1) & 3)) << 2)) * 4u;
    unsigned so1 = (unsigned)(cm1 * 16 + ((cc1 ^ ((cm1 >> 1) & 3)) << 2)) * 4u;
    const float* ag0 = Ag + (size_t)cm0 * C_DIM + cc0 * 4;
    const float* ag1 = Ag + (size_t)cm1 * C_DIM + cc1 * 4;
    const float* wg0 = Wg + (size_t)cm0 * C_DIM + cc0 * 4;
    const float* wg1 = Wg + (size_t)cm1 * C_DIM + cc1 * 4;

    int lr8 = lane & 7;
    int tq  = lane >> 3;
    unsigned aoff[4]; int akey[4];
#pragma unroll
    for (int mt = 0; mt < 4; mt++) {
        int arow = wm * 64 + mt * 16 + ((tq & 1) << 3) + lr8;
        aoff[mt] = (unsigned)(arow * 16);
        akey[mt] = (arow >> 1) & 3;
    }
    int akgh = tq >> 1;
    unsigned boff[2]; int bkey[2];
#pragma unroll
    for (int p = 0; p < 2; p++) {
        int brow = wn * 32 + p * 16 + ((lane >> 4) << 3) + lr8;
        boff[p] = (unsigned)(brow * 16);
        bkey[p] = (brow >> 1) & 3;
    }
    int bkgh = tq & 1;

    float acc[4][4][4];
#pragma unroll
    for (int mt = 0; mt < 4; mt++)
#pragma unroll
        for (int nt = 0; nt < 4; nt++)
#pragma unroll
            for (int i = 0; i < 4; i++) acc[mt][nt][i] = 0.f;

#pragma unroll
    for (int s = 0; s < 4; s++) {
        unsigned sb = sbase + (unsigned)(s * STG_FLOATS) * 4u;
        cpasync16(sb + so0, ag0 + s * KC);
        cpasync16(sb + so1, ag1 + s * KC);
        cpasync16(sb + 2048 * 4 + so0, wg0 + s * KC);
        cpasync16(sb + 2048 * 4 + so1, wg1 + s * KC);
        asm volatile("cp.async.commit_group;");
    }

    for (int s = 0; s < NSTG; s++) {
        if (s < NSTG - 3)       asm volatile("cp.async.wait_group 3;");
        else if (s == NSTG - 3) asm volatile("cp.async.wait_group 2;");
        else if (s == NSTG - 2) asm volatile("cp.async.wait_group 1;");
        else                    asm volatile("cp.async.wait_group 0;");
        __syncthreads();

        if (s + 4 < NSTG) {
            int sn = s + 4;
            unsigned sb = sbase + (unsigned)((sn % STAGES) * STG_FLOATS) * 4u;
            cpasync16(sb + so0, ag0 + sn * KC);
            cpasync16(sb + so1, ag1 + sn * KC);
            cpasync16(sb + 2048 * 4 + so0, wg0 + sn * KC);
            cpasync16(sb + 2048 * 4 + so1, wg1 + sn * KC);
            asm volatile("cp.async.commit_group;");
        }

        unsigned stw = sbase + (unsigned)((s % STAGES) * STG_FLOATS) * 4u;
#pragma unroll
        for (int ks = 0; ks < 2; ks++) {
            unsigned af[4][4], bq2[2][4];
#pragma unroll
            for (int mt = 0; mt < 4; mt++) {
                int kg = 2 * ks + akgh;
                unsigned ad = stw + (aoff[mt] + (unsigned)((kg ^ akey[mt]) << 2)) * 4u;
                ldsm4(af[mt], ad);
            }
#pragma unroll
            for (int p = 0; p < 2; p++) {
                int kg = 2 * ks + bkgh;
                unsigned bd = stw + 2048 * 4u +
                              (boff[p] + (unsigned)((kg ^ bkey[p]) << 2)) * 4u;
                ldsm4(bq2[p], bd);
            }
#pragma unroll
            for (int mt = 0; mt < 4; mt++)
#pragma unroll
                for (int nt = 0; nt < 4; nt++) {
                    int p = nt >> 1, o = (nt & 1) * 2;
                    mma_tf32(acc[mt][nt], af[mt][0], af[mt][1], af[mt][2],
                             af[mt][3], bq2[p][o], bq2[p][o + 1]);
                }
        }
    }

    float* qkvbase = (sel == 0) ? g_q : (sel == 1) ? g_k : g_v;
    int cc = lane & 3, lrr = lane >> 2;
#pragma unroll
    for (int mt = 0; mt < 4; mt++) {
#pragma unroll
        for (int half = 0; half < 2; half++) {
            int gm = m0 + wm * 64 + mt * 16 + lrr + half * 8;
            int b_ = gm / N_TOK;
            int t  = gm - b_ * N_TOK;
#pragma unroll
            for (int nt = 0; nt < 4; nt++) {
                int gn = n0 + wn * 32 + nt * 8 + cc * 2;
                float v0 = acc[mt][nt][half * 2 + 0] + bias[gn];
                float v1 = acc[mt][nt][half * 2 + 1] + bias[gn + 1];
                float* dst;
                if (sel == 3) {
                    dst = outPlain + (size_t)gm * C_DIM + gn;
                } else {
                    int h = gn >> 6, d = gn & 63;
                    dst = qkvbase +
                          ((((size_t)b_ * H_NUM + h) * N_TOK + t) * HD + d);
                }
                *(float2*)dst = make_float2(v0, v1);
            }
        }
    }
}

// ---------------------------------------------------------------------------
// Tensor-core window attention.  One block per (b_,h), 288 threads = 9 warps.
// Warp w owns rows [16w, 16w+16) (144 window rows; row 144 done by gx).
// S = Q K^T via mma (19 n-tiles of 8, K padded to 160 rows);
// softmax in accumulator registers (quad shuffles);
// P re-laid to A-fragments via 8 warp shuffles per kstep;
// O = P V via mma with V^T staged [d][n].
// K smem: 160x64 fp32, word (n,k): n*64+(((k>>2&8)|((k>>2&7)^(n&7)))<<2)+(k&3)
// Vt smem: 64x160 fp32, word (d,n): d*160+((((n>>2)&~7)|((n>>2&7)^(d&7)))<<2)+(n&3)
// Both verified conflict-free for 8-row ldmatrix phases.
// ---------------------------------------------------------------------------
#define AT_SMEM_BYTES ((160 * 64 + 64 * 160) * 4)   // 81920

__global__ void __launch_bounds__(288, 1) attn_kernel()
{
    extern __shared__ __align__(16) float sm[];
    float* Ks = sm;              // 160 x 64
    float* Vt = sm + 160 * 64;   // 64 x 160

    int bh = blockIdx.x;
    int b_ = bh >> 3, h = bh & 7, w = b_ & 3;
    const float* gK = g_k + (size_t)bh * (N_TOK * HD);
    const float* gV = g_v + (size_t)bh * (N_TOK * HD);
    const float* gQ = g_q + (size_t)bh * (N_TOK * HD);
    const float* comb = g_comb[w * 8 + h];
    int tid = threadIdx.x, lane = tid & 31, warp = tid / 32;

    // Stage K [n][k] swizzled, rows >=145 zero
    for (int i = tid; i < 160 * 64; i += 288) {
        int n = i >> 6, k = i & 63;
        int g = k >> 2;
        int off = n * 64 + (((g & 8) | ((g & 7) ^ (n & 7))) << 2) + (k & 3);
        Ks[off] = (n < N_TOK) ? tf32f(gK[n * 64 + k]) : 0.f;
    }
    // Stage V transposed [d][n] swizzled, cols >=145 zero
    for (int i = tid; i < 160 * 64; i += 288) {
        int n = i >> 6, d = i & 63;
        int g = n >> 2;
        int off = d * 160 + ((((g & ~7) | ((g & 7) ^ (d & 7)))) << 2) + (n & 3);
        Vt[off] = (n < N_TOK) ? tf32f(gV[n * 64 + d]) : 0.f;
    }

    int c = lane & 3, lr = lane >> 2;
    int m0 = warp * 16;

    // Q in registers, A-fragment layout, tf32-rounded
    float aq[8][4];
    {
        const float* q0 = gQ + (m0 + lr) * 64;
        const float* q1 = gQ + (m0 + lr + 8) * 64;
#pragma unroll
        for (int ks = 0; ks < 8; ks++) {
            aq[ks][0] = tf32f(q0[8 * ks + c]);
            aq[ks][1] = tf32f(q1[8 * ks + c]);
            aq[ks][2] = tf32f(q0[8 * ks + c + 4]);
            aq[ks][3] = tf32f(q1[8 * ks + c + 4]);
        }
    }
    __syncthreads();

    // ldmatrix lane geometry
    int rowLocal = ((lane >> 4) << 3) + (lane & 7);
    int kbit = (lane >> 3) & 1;
    int rk7 = rowLocal & 7;

    unsigned ksBase = (unsigned)__cvta_generic_to_shared(Ks);
    unsigned vtBase = (unsigned)__cvta_generic_to_shared(Vt);

    float sacc[19][4];
#pragma unroll
    for (int t = 0; t < 19; t++)
#pragma unroll
        for (int i = 0; i < 4; i++) sacc[t][i] = 0.f;

    // ---- S = Q K^T ----
#pragma unroll
    for (int ks = 0; ks < 8; ks++) {
        int kg = 2 * ks + kbit;
        unsigned sw = (unsigned)(((kg & 8) | ((kg & 7) ^ rk7)) << 2);
        unsigned a0 = __float_as_uint(aq[ks][0]);
        unsigned a1 = __float_as_uint(aq[ks][1]);
        unsigned a2 = __float_as_uint(aq[ks][2]);
        unsigned a3 = __float_as_uint(aq[ks][3]);
#pragma unroll
        for (int tp = 0; tp < 10; tp++) {
            unsigned addr = ksBase +
                ((unsigned)((16 * tp + rowLocal) * 64) + sw) * 4u;
            unsigned br[4];
            ldsm4(br, addr);
            mma_tf32(sacc[2 * tp], a0, a1, a2, a3, br[0], br[1]);
            if (2 * tp + 1 < 19)
                mma_tf32(sacc[2 * tp + 1], a0, a1, a2, a3, br[2], br[3]);
        }
    }

    // ---- softmax in registers ----
    const float* crow0 = comb + (m0 + lr) * 152 + 2 * c;
    const float* crow1 = comb + (m0 + lr + 8) * 152 + 2 * c;
    float mx0 = -1e30f, mx1 = -1e30f;
#pragma unroll
    for (int t = 0; t < 19; t++) {
        float2 cb0 = *(const float2*)(crow0 + 8 * t);
        float2 cb1 = *(const float2*)(crow1 + 8 * t);
        sacc[t][0] = sacc[t][0] * 0.125f + cb0.x;
        sacc[t][1] = sacc[t][1] * 0.125f + cb0.y;
        sacc[t][2] = sacc[t][2] * 0.125f + cb1.x;
        sacc[t][3] = sacc[t][3] * 0.125f + cb1.y;
        mx0 = fmaxf(mx0, fmaxf(sacc[t][0], sacc[t][1]));
        mx1 = fmaxf(mx1, fmaxf(sacc[t][2], sacc[t][3]));
    }
    mx0 = fmaxf(mx0, __shfl_xor_sync(0xffffffffu, mx0, 1));
    mx0 = fmaxf(mx0, __shfl_xor_sync(0xffffffffu, mx0, 2));
    mx1 = fmaxf(mx1, __shfl_xor_sync(0xffffffffu, mx1, 1));
    mx1 = fmaxf(mx1, __shfl_xor_sync(0xffffffffu, mx1, 2));

    float l0 = 0.f, l1 = 0.f;
#pragma unroll
    for (int t = 0; t < 19; t++) {
        float p0 = __expf(sacc[t][0] - mx0);
        float p1 = __expf(sacc[t][1] - mx0);
        float p2 = __expf(sacc[t][2] - mx1);
        float p3 = __expf(sacc[t][3] - mx1);
        l0 += p0 + p1;
        l1 += p2 + p3;
        sacc[t][0] = tf32f(p0);
        sacc[t][1] = tf32f(p1);
        sacc[t][2] = tf32f(p2);
        sacc[t][3] = tf32f(p3);
    }
    l0 += __shfl_xor_sync(0xffffffffu, l0, 1);
    l0 += __shfl_xor_sync(0xffffffffu, l0, 2);
    l1 += __shfl_xor_sync(0xffffffffu, l1, 1);
    l1 += __shfl_xor_sync(0xffffffffu, l1, 2);

    // ---- O = P V ----
    float pacc[8][4];
#pragma unroll
    for (int dt = 0; dt < 8; dt++)
#pragma unroll
        for (int i = 0; i < 4; i++) pacc[dt][i] = 0.f;

    int src  = (lr << 2) + (c >> 1);
    int src2 = src + 2;
    bool odd = (c & 1) != 0;
#pragma unroll
    for (int kk = 0; kk < 19; kk++) {
        float s0 = __shfl_sync(0xffffffffu, sacc[kk][0], src);
        float s1 = __shfl_sync(0xffffffffu, sacc[kk][1], src);
        float s2 = __shfl_sync(0xffffffffu, sacc[kk][2], src);
        float s3 = __shfl_sync(0xffffffffu, sacc[kk][3], src);
        float t0 = __shfl_sync(0xffffffffu, sacc[kk][0], src2);
        float t1 = __shfl_sync(0xffffffffu, sacc[kk][1], src2);
        float t2 = __shfl_sync(0xffffffffu, sacc[kk][2], src2);
        float t3 = __shfl_sync(0xffffffffu, sacc[kk][3], src2);
        unsigned a0 = __float_as_uint(odd ? s1 : s0);
        unsigned a1 = __float_as_uint(odd ? s3 : s2);
        unsigned a2 = __float_as_uint(odd ? t1 : t0);
        unsigned a3 = __float_as_uint(odd ? t3 : t2);

        int kg = 2 * kk + kbit;
        unsigned sw = (unsigned)((((kg & ~7) | ((kg & 7) ^ rk7))) << 2);
#pragma unroll
        for (int p = 0; p < 4; p++) {
            unsigned addr = vtBase +
                ((unsigned)((16 * p + rowLocal) * 160) + sw) * 4u;
            unsigned br[4];
            ldsm4(br, addr);
            mma_tf32(pacc[2 * p],     a0, a1, a2, a3, br[0], br[1]);
            mma_tf32(pacc[2 * p + 1], a0, a1, a2, a3, br[2], br[3]);
        }
    }

    float inv0 = 1.f / l0, inv1 = 1.f / l1;
    float* dst0 = g_opre + (size_t)(b_ * N_TOK + m0 + lr) * C_DIM + h * HD;
    float* dst1 = dst0 + 8 * C_DIM;
#pragma unroll
    for (int dt = 0; dt < 8; dt++) {
        *(float2*)(dst0 + dt * 8 + 2 * c) =
            make_float2(tf32f(pacc[dt][0] * inv0), tf32f(pacc[dt][1] * inv0));
        *(float2*)(dst1 + dt * 8 + 2 * c) =
            make_float2(tf32f(pacc[dt][2] * inv1), tf32f(pacc[dt][3] * inv1));
    }
}

// ---------------------------------------------------------------------------
// Global-token redistribution: one block per (b, h).  (unchanged)
// ---------------------------------------------------------------------------
__global__ void __launch_bounds__(128) gx_kernel(const float* __restrict__ mask)
{
    __shared__ __align__(16) float L[580];
    __shared__ __align__(16) float Qg[256];
    __shared__ __align__(16) float red[128];
    __shared__ float s_inv;

    int b = blockIdx.x >> 3, h = blockIdx.x & 7;
    int tid = threadIdx.x;

    for (int i = tid; i < 256; i += 128) {
        int w = i >> 6, d = i & 63;
        Qg[i] = g_q[(((size_t)(b * 4 + w) * H_NUM + h) * N_TOK + M_TOK) * HD + d];
    }
    __syncthreads();

    for (int idx = tid; idx < 577; idx += 128) {
        if (idx < 576) {
            int w = idx / 144, n = idx - w * 144;
            const float4* kp = (const float4*)(g_k +
                (((size_t)(b * 4 + w) * H_NUM + h) * N_TOK + n) * HD);
            const float4* qp = (const float4*)(Qg + w * 64);
            float dot = 0.f;
#pragma unroll
            for (int t = 0; t < 16; t++) {
                float4 kv = kp[t], qv = qp[t];
                dot += kv.x * qv.x + kv.y * qv.y + kv.z * qv.z + kv.w * qv.w;
            }
            L[idx] = dot * 0.125f +
                     mask[(size_t)w * (N_TOK * N_TOK) + M_TOK * N_TOK + n];
        } else {
            float s = 0.f;
            for (int w = 0; w < 4; w++) {
                const float4* kp = (const float4*)(g_k +
                    (((size_t)(b * 4 + w) * H_NUM + h) * N_TOK + M_TOK) * HD);
                const float4* qp = (const float4*)(Qg + w * 64);
                float dot = 0.f;
#pragma unroll
                for (int t = 0; t < 16; t++) {
                    float4 kv = kp[t], qv = qp[t];
                    dot += kv.x * qv.x + kv.y * qv.y + kv.z * qv.z + kv.w * qv.w;
                }
                s += dot * 0.125f +
                     mask[(size_t)w * (N_TOK * N_TOK) + M_TOK * N_TOK + M_TOK];
            }
            L[576] = s * 0.25f;
        }
    }
    __syncthreads();

    float mx = -1e30f;
    for (int idx = tid; idx < 577; idx += 128) mx = fmaxf(mx, L[idx]);
    red[tid] = mx;
    __syncthreads();
    for (int s2 = 64; s2 > 0; s2 >>= 1) {
        if (tid < s2) red[tid] = fmaxf(red[tid], red[tid + s2]);
        __syncthreads();
    }
    mx = red[0];
    __syncthreads();

    float ps = 0.f;
    for (int idx = tid; idx < 577; idx += 128) {
        float e = __expf(L[idx] - mx);
        L[idx] = e;
        ps += e;
    }
    red[tid] = ps;
    __syncthreads();
    for (int s2 = 64; s2 > 0; s2 >>= 1) {
        if (tid < s2) red[tid] += red[tid + s2];
        __syncthreads();
    }
    if (tid == 0) s_inv = 1.f / red[0];
    __syncthreads();

    int d = tid & 63, half = tid >> 6;
    float acc = 0.f;
    for (int w = 0; w < 4; w++) {
        const float* vb = g_v + (((size_t)(b * 4 + w) * H_NUM + h) * N_TOK) * HD;
        for (int n = half; n < M_TOK; n += 2)
            acc += L[w * 144 + n] * vb[n * HD + d];
        if ((w & 1) == half)
            acc += L[576] * vb[M_TOK * HD + d];
    }
    red[tid] = acc;
    __syncthreads();
    if (half == 0) {
        float tot = tf32f((red[tid] + red[tid + 64]) * s_inv);
#pragma unroll
        for (int w = 0; w < 4; w++)
            g_opre[(size_t)((b * 4 + w) * N_TOK + M_TOK) * C_DIM + h * HD + d] = tot;
    }
}

// ---------------------------------------------------------------------------
extern "C" void kernel_launch(void* const* d_in, const int* in_sizes, int n_in,
                              void* d_out, int out_size)
{
    const float* x    = (const float*)d_in[0];
    const float* mask = (const float*)d_in[1];
    const float* rpb  = (const float*)d_in[2];
    const float* Wq   = (const float*)d_in[3];
    const float* bq   = (const float*)d_in[4];
    const float* Wk   = (const float*)d_in[5];
    const float* bk   = (const float*)d_in[6];
    const float* Wv   = (const float*)d_in[7];
    const float* bv   = (const float*)d_in[8];
    const float* Wo   = (const float*)d_in[9];
    const float* bo   = (const float*)d_in[10];
    float* out = (float*)d_out;

    cudaFuncSetAttribute(tgemm, cudaFuncAttributeMaxDynamicSharedMemorySize,
                         TGEMM_SMEM_BYTES);
    cudaFuncSetAttribute(attn_kernel, cudaFuncAttributeMaxDynamicSharedMemorySize,
                         AT_SMEM_BYTES);

    cvt_x_kernel<<<ROWS * C_DIM / 1024, 256>>>(x);
    cvt_w_kernel<<<dim3(C_DIM * C_DIM / 1024, 4), 256>>>(Wq, Wk, Wv, Wo);
    comb_kernel<<<dim3(N_TOK, NWIN * H_NUM), 160>>>(mask, rpb);

    dim3 gg(4, 580, 1);   // 512/128 x 74240/128
    tgemm<<<gg, 256, TGEMM_SMEM_BYTES>>>(bq, nullptr, 0);
    tgemm<<<gg, 256, TGEMM_SMEM_BYTES>>>(bk, nullptr, 1);
    tgemm<<<gg, 256, TGEMM_SMEM_BYTES>>>(bv, nullptr, 2);

    attn_kernel<<<4096, 288, AT_SMEM_BYTES>>>();
    gx_kernel<<<1024, 128>>>(mask);

    tgemm<<<gg, 256, TGEMM_SMEM_BYTES>>>(bo, out, 3);
}